// round 8
// baseline (speedup 1.0000x reference)
#include <cuda_runtime.h>
#include <cuda_bf16.h>
#include <math.h>
#include <cstdint>

// Shapes
#define Bz 64
#define Hh 1024
#define Vv 32000
#define Ss 512
#define Ee 2048   // 2H
#define H3 3072   // 3H
#define H4 4096   // 4H
#define KC 32

// ---------------- scratch ----------------
__device__ __align__(16) float g_x[Bz * Hh];
__device__ __align__(16) float g_part[16 * Bz * Ee];   // 2M floats (fits all split-K uses)
__device__ __align__(16) float g_scores[Bz * Ss];
__device__ __align__(16) float g_cin[Bz * H3];
__device__ __align__(16) float g_cc[Bz * H3];
__device__ __align__(16) float g_ctxp[4 * Bz * Ee];
__device__ __align__(16) float g_ml[4 * Bz * 2];

// ================= mma helpers =================
__device__ __forceinline__ void mma16816(float c[4],
    uint32_t a0, uint32_t a1, uint32_t a2, uint32_t a3,
    uint32_t b0, uint32_t b1)
{
    asm volatile(
        "mma.sync.aligned.m16n8k16.row.col.f32.bf16.bf16.f32 "
        "{%0,%1,%2,%3}, {%4,%5,%6,%7}, {%8,%9}, {%0,%1,%2,%3};"
        : "+f"(c[0]), "+f"(c[1]), "+f"(c[2]), "+f"(c[3])
        : "r"(a0), "r"(a1), "r"(a2), "r"(a3), "r"(b0), "r"(b1));
}

__device__ __forceinline__ void cvt4(float4 v, __nv_bfloat16* hi, __nv_bfloat16* lo)
{
    __nv_bfloat16 hx = __float2bfloat16_rn(v.x);
    __nv_bfloat16 hy = __float2bfloat16_rn(v.y);
    __nv_bfloat16 hz = __float2bfloat16_rn(v.z);
    __nv_bfloat16 hw = __float2bfloat16_rn(v.w);
    __nv_bfloat162 h01 = __halves2bfloat162(hx, hy);
    __nv_bfloat162 h23 = __halves2bfloat162(hz, hw);
    *(uint2*)hi = make_uint2(*(uint32_t*)&h01, *(uint32_t*)&h23);
    __nv_bfloat162 l01 = __halves2bfloat162(
        __float2bfloat16_rn(v.x - __bfloat162float(hx)),
        __float2bfloat16_rn(v.y - __bfloat162float(hy)));
    __nv_bfloat162 l23 = __halves2bfloat162(
        __float2bfloat16_rn(v.z - __bfloat162float(hz)),
        __float2bfloat16_rn(v.w - __bfloat162float(hw)));
    *(uint2*)lo = make_uint2(*(uint32_t*)&l01, *(uint32_t*)&l23);
}

// ============ GEMM v3: A direct-from-gmem fragments, B-only smem ============
// CTA: 128 N-rows (weights) x 64 batch. 8 warps, warp tile 16x64 (wm only).
// A fragments: per thread float2 loads at the exact mma ownership positions,
// fp32 -> bf16 hi/lo split done in registers (no smem round trip, no dup).
// B (cc/act tile, 64 x KC): smem hi/lo, stride 40 (conflict-free b32 frags).
// 3-split: Ah*Bh + Ah*Bl + Al*Bh.
// BLAYOUT 0: W[N,K] k-contig. BLAYOUT 1: W[K,N] (scalar gathers).
// MODE 0: partial write (no bias). MODE 1: final write + bias.

#define BSEG 2560   // 64*40 elems per (buf,hi/lo) segment

template<int BLAYOUT, int MODE>
__device__ __forceinline__ void gemm3_body(
    const float* __restrict__ W, const float* __restrict__ act,
    float* __restrict__ dst, const float* __restrict__ bias,
    int N, int K, int kChunks, int n0, int kBase, __nv_bfloat16* Bs)
{
    const int tid  = threadIdx.x;
    const int lane = tid & 31;
    const int wm   = tid >> 5;
    const int rg   = lane >> 2;
    const int kq   = (lane & 3) * 2;

    const int r0 = n0 + wm * 16 + rg;     // this thread's A row (and r0+8)

    const int ar = tid >> 3;              // B loader batch row 0..31 (+32)
    const int cg = (tid & 7) * 4;         // B loader k offset

    float acc[8][4] = {};

    float2 pa[2][4];                      // [row-half][g], g: k = kq + g*8
    float4 pbv[2];

    auto loadA = [&](int k0) {
        if (BLAYOUT == 0) {
            const float* p0 = W + (size_t)r0 * K + k0 + kq;
            const float* p1 = p0 + (size_t)8 * K;
            #pragma unroll
            for (int g = 0; g < 4; ++g) {
                pa[0][g] = *(const float2*)(p0 + g * 8);
                pa[1][g] = *(const float2*)(p1 + g * 8);
            }
        } else {
            #pragma unroll
            for (int g = 0; g < 4; ++g) {
                int k = k0 + kq + g * 8;
                pa[0][g].x = W[(size_t)k * N + r0];
                pa[0][g].y = W[(size_t)(k + 1) * N + r0];
                pa[1][g].x = W[(size_t)k * N + r0 + 8];
                pa[1][g].y = W[(size_t)(k + 1) * N + r0 + 8];
            }
        }
    };
    auto loadB = [&](int k0) {
        pbv[0] = *(const float4*)&act[(size_t)ar * K + k0 + cg];
        pbv[1] = *(const float4*)&act[(size_t)(ar + 32) * K + k0 + cg];
    };
    auto storeB = [&](int buf) {
        __nv_bfloat16* BH = Bs + (buf * 2 + 0) * BSEG;
        __nv_bfloat16* BL = Bs + (buf * 2 + 1) * BSEG;
        cvt4(pbv[0], BH + ar * 40 + cg, BL + ar * 40 + cg);
        cvt4(pbv[1], BH + (ar + 32) * 40 + cg, BL + (ar + 32) * 40 + cg);
    };

    loadA(kBase);
    loadB(kBase);
    storeB(0);
    __syncthreads();

    for (int ch = 0; ch < kChunks; ++ch) {
        const int cur = ch & 1;

        // convert A prefetch regs -> bf16 hi/lo fragments (in registers)
        uint32_t ah[2][4], al[2][4];
        #pragma unroll
        for (int ks = 0; ks < 2; ++ks)
            #pragma unroll
            for (int half = 0; half < 2; ++half) {
                const int g = ks * 2 + half;
                #pragma unroll
                for (int h = 0; h < 2; ++h) {
                    float x = pa[h][g].x, y = pa[h][g].y;
                    __nv_bfloat162 hh = __floats2bfloat162_rn(x, y);
                    __nv_bfloat162 ll = __floats2bfloat162_rn(
                        x - __bfloat162float(hh.x), y - __bfloat162float(hh.y));
                    ah[ks][half * 2 + h] = *(uint32_t*)&hh;
                    al[ks][half * 2 + h] = *(uint32_t*)&ll;
                }
            }

        // prefetch next chunk into regs (A regs free after conversion)
        if (ch + 1 < kChunks) {
            loadA(kBase + (ch + 1) * KC);
            loadB(kBase + (ch + 1) * KC);
        }

        // mma phase
        const __nv_bfloat16* BH = Bs + (cur * 2 + 0) * BSEG;
        const __nv_bfloat16* BL = Bs + (cur * 2 + 1) * BSEG;
        #pragma unroll
        for (int ks = 0; ks < 2; ++ks) {
            const int ko = ks * 16 + kq;
            #pragma unroll
            for (int nt = 0; nt < 8; ++nt) {
                const __nv_bfloat16* ph = BH + (nt * 8 + rg) * 40 + ko;
                const __nv_bfloat16* pl = BL + (nt * 8 + rg) * 40 + ko;
                uint32_t bh0 = *(const uint32_t*)ph;
                uint32_t bh1 = *(const uint32_t*)(ph + 8);
                uint32_t bl0 = *(const uint32_t*)pl;
                uint32_t bl1 = *(const uint32_t*)(pl + 8);
                mma16816(acc[nt], ah[ks][0], ah[ks][1], ah[ks][2], ah[ks][3], bh0, bh1);
                mma16816(acc[nt], ah[ks][0], ah[ks][1], ah[ks][2], ah[ks][3], bl0, bl1);
                mma16816(acc[nt], al[ks][0], al[ks][1], al[ks][2], al[ks][3], bh0, bh1);
            }
        }

        if (ch + 1 < kChunks) storeB(1 - cur);
        __syncthreads();
    }

    // epilogue: direct stores from accumulators
    {
        float b0v = 0.f, b1v = 0.f;
        if (MODE == 1) { b0v = bias[r0]; b1v = bias[r0 + 8]; }
        #pragma unroll
        for (int nt = 0; nt < 8; ++nt) {
            int b = nt * 8 + kq;
            dst[(size_t)b * N + r0]           = acc[nt][0] + b0v;
            dst[(size_t)(b + 1) * N + r0]     = acc[nt][1] + b0v;
            dst[(size_t)b * N + r0 + 8]       = acc[nt][2] + b1v;
            dst[(size_t)(b + 1) * N + r0 + 8] = acc[nt][3] + b1v;
        }
    }
}

template<int BLAYOUT>
__global__ void __launch_bounds__(256, 2) k3_part(
    const float* __restrict__ W, const float* __restrict__ act,
    float* __restrict__ parts, int N, int K, int kChunks)
{
    __shared__ __align__(16) __nv_bfloat16 Bs[4 * BSEG];
    gemm3_body<BLAYOUT, 0>(W, act, parts + (size_t)blockIdx.y * 64 * N, nullptr,
                           N, K, kChunks, blockIdx.x * 128,
                           blockIdx.y * kChunks * KC, Bs);
}

__global__ void __launch_bounds__(256, 2) k3_dual(
    const float* __restrict__ W0, const float* __restrict__ W1,
    const float* __restrict__ a0, const float* __restrict__ a1,
    float* __restrict__ parts, int N, int K, int kChunks)
{
    __shared__ __align__(16) __nv_bfloat16 Bs[4 * BSEG];
    const float* W = blockIdx.z ? W1 : W0;
    const float* A = blockIdx.z ? a1 : a0;
    int slice = blockIdx.y + 4 * blockIdx.z;
    gemm3_body<0, 0>(W, A, parts + (size_t)slice * 64 * N, nullptr,
                     N, K, kChunks, blockIdx.x * 128,
                     blockIdx.y * kChunks * KC, Bs);
}

__global__ void __launch_bounds__(256, 2) k3_direct(
    const float* __restrict__ W, const float* __restrict__ act,
    float* __restrict__ out, const float* __restrict__ bias,
    int N, int K, int kChunks)
{
    __shared__ __align__(16) __nv_bfloat16 Bs[4 * BSEG];
    gemm3_body<0, 1>(W, act, out, bias, N, K, kChunks, blockIdx.x * 128, 0, Bs);
}

// ================= split-K reduce for concat (+bias +tanh) =================
template<int NSL>
__global__ void reduceN(const float* __restrict__ parts,
                        const float* __restrict__ b1,
                        float* __restrict__ C, int N)
{
    int i4 = blockIdx.x * 256 + threadIdx.x;
    const float4* p4 = (const float4*)parts;
    float4 s = p4[i4];
    #pragma unroll
    for (int sl = 1; sl < NSL; ++sl) {
        float4 v = p4[(size_t)sl * (64 * N / 4) + i4];
        s.x += v.x; s.y += v.y; s.z += v.z; s.w += v.w;
    }
    int n4 = i4 % (N / 4);
    float4 bv = ((const float4*)b1)[n4];
    s.x = tanhf(s.x + bv.x);
    s.y = tanhf(s.y + bv.y);
    s.z = tanhf(s.z + bv.z);
    s.w = tanhf(s.w + bv.w);
    ((float4*)C)[i4] = s;
}

// ================= pointwise =================
__global__ void gather_k(const int* __restrict__ seq, const float* __restrict__ emb,
                         float* __restrict__ x)
{
    int idx = blockIdx.x * 256 + threadIdx.x;
    int b = idx >> 10;
    x[idx] = emb[(size_t)seq[b] * Hh + (idx & 1023)];
}

__device__ __forceinline__ float sigf(float x) { return 1.f / (1.f + expf(-x)); }

__global__ void lstm_pw2(const float* __restrict__ parts,
                         const float* __restrict__ b_ih, const float* __restrict__ b_hh,
                         const float* __restrict__ c0,
                         float* __restrict__ h_out, float* __restrict__ c_out,
                         float* __restrict__ cin)
{
    int idx = blockIdx.x * 256 + threadIdx.x;   // 64*1024
    int b = idx >> 10, h = idx & 1023;
    float gate[4];
    #pragma unroll
    for (int g = 0; g < 4; ++g) {
        int n = g * Hh + h;
        float s = b_ih[n] + b_hh[n];
        #pragma unroll
        for (int sl = 0; sl < 8; ++sl)
            s += parts[(size_t)sl * 64 * H4 + (size_t)b * H4 + n];
        gate[g] = s;
    }
    float ig = sigf(gate[0]);
    float fg = sigf(gate[1]);
    float gg = tanhf(gate[2]);
    float og = sigf(gate[3]);
    float c = fg * c0[idx] + ig * gg;
    float hn = og * tanhf(c);
    c_out[idx] = c;
    h_out[idx] = hn;
    cin[(size_t)b * H3 + h] = hn;
}

// ================= single-pass split-S attention (4-s batched) =================
__global__ void __launch_bounds__(256) att_split(
    const float* __restrict__ qparts, const float* __restrict__ enc,
    float* __restrict__ scores, float* __restrict__ ctxp, float* __restrict__ ml)
{
    __shared__ float wsum[2][8][4];
    const int b = blockIdx.y, sp = blockIdx.x;
    const int tid = threadIdx.x, lane = tid & 31, w = tid >> 5;
    const int e0 = tid * 4;

    // q = sum of 16 split-K partial slices (N = Ee)
    float4 q0 = make_float4(0.f, 0.f, 0.f, 0.f);
    float4 q1 = make_float4(0.f, 0.f, 0.f, 0.f);
    #pragma unroll
    for (int sl = 0; sl < 16; ++sl) {
        const float* qp = qparts + (size_t)sl * 64 * Ee + (size_t)b * Ee;
        float4 a = *(const float4*)&qp[e0];
        float4 c = *(const float4*)&qp[1024 + e0];
        q0.x += a.x; q0.y += a.y; q0.z += a.z; q0.w += a.w;
        q1.x += c.x; q1.y += c.y; q1.z += c.z; q1.w += c.w;
    }

    float m = -INFINITY, l = 0.f;
    float4 c0 = make_float4(0.f, 0.f, 0.f, 0.f);
    float4 c1 = make_float4(0.f, 0.f, 0.f, 0.f);

    const int sBeg = sp * 128;
    const float* base = enc + (size_t)b * Ee + e0;

    float4 ce[4][2];
    #pragma unroll
    for (int j = 0; j < 4; ++j) {
        ce[j][0] = *(const float4*)&base[(size_t)(sBeg + j) * (Bz * Ee)];
        ce[j][1] = *(const float4*)&base[(size_t)(sBeg + j) * (Bz * Ee) + 1024];
    }

    for (int g = 0; g < 32; ++g) {
        const int s0 = sBeg + g * 4;
        const int buf = g & 1;

        float d[4];
        #pragma unroll
        for (int j = 0; j < 4; ++j)
            d[j] = q0.x * ce[j][0].x + q0.y * ce[j][0].y + q0.z * ce[j][0].z + q0.w * ce[j][0].w
                 + q1.x * ce[j][1].x + q1.y * ce[j][1].y + q1.z * ce[j][1].z + q1.w * ce[j][1].w;

        float4 ne[4][2];
        if (g < 31) {
            #pragma unroll
            for (int j = 0; j < 4; ++j) {
                ne[j][0] = *(const float4*)&base[(size_t)(s0 + 4 + j) * (Bz * Ee)];
                ne[j][1] = *(const float4*)&base[(size_t)(s0 + 4 + j) * (Bz * Ee) + 1024];
            }
        }

        #pragma unroll
        for (int o = 16; o; o >>= 1)
            #pragma unroll
            for (int j = 0; j < 4; ++j)
                d[j] += __shfl_xor_sync(0xffffffffu, d[j], o);
        if (lane < 4) wsum[buf][w][lane] = d[lane];
        __syncthreads();

        float sc[4];
        #pragma unroll
        for (int j = 0; j < 4; ++j) {
            float s = 0.f;
            #pragma unroll
            for (int ww = 0; ww < 8; ++ww) s += wsum[buf][ww][j];
            sc[j] = s;
        }
        if (tid < 4) scores[b * Ss + s0 + tid] = sc[tid];

        float mloc = fmaxf(fmaxf(sc[0], sc[1]), fmaxf(sc[2], sc[3]));
        float mn = fmaxf(m, mloc);
        float scale = __expf(m - mn);
        float pw[4];
        float psum = 0.f;
        #pragma unroll
        for (int j = 0; j < 4; ++j) { pw[j] = __expf(sc[j] - mn); psum += pw[j]; }
        l = l * scale + psum;
        c0.x = c0.x * scale; c0.y = c0.y * scale; c0.z = c0.z * scale; c0.w = c0.w * scale;
        c1.x = c1.x * scale; c1.y = c1.y * scale; c1.z = c1.z * scale; c1.w = c1.w * scale;
        #pragma unroll
        for (int j = 0; j < 4; ++j) {
            c0.x += pw[j] * ce[j][0].x; c0.y += pw[j] * ce[j][0].y;
            c0.z += pw[j] * ce[j][0].z; c0.w += pw[j] * ce[j][0].w;
            c1.x += pw[j] * ce[j][1].x; c1.y += pw[j] * ce[j][1].y;
            c1.z += pw[j] * ce[j][1].z; c1.w += pw[j] * ce[j][1].w;
        }
        m = mn;
        #pragma unroll
        for (int j = 0; j < 4; ++j) { ce[j][0] = ne[j][0]; ce[j][1] = ne[j][1]; }
    }

    float* cp = ctxp + ((size_t)sp * Bz + b) * Ee;
    *(float4*)&cp[e0] = c0;
    *(float4*)&cp[1024 + e0] = c1;
    if (tid == 0) {
        ml[(sp * Bz + b) * 2 + 0] = m;
        ml[(sp * Bz + b) * 2 + 1] = l;
    }
}

__global__ void __launch_bounds__(256) att_combine(
    const float* __restrict__ ctxp, const float* __restrict__ ml,
    const float* __restrict__ scores, float* __restrict__ cin,
    float* __restrict__ aw_out)
{
    const int b = blockIdx.x, tid = threadIdx.x;
    float m0 = ml[(0 * Bz + b) * 2], l0 = ml[(0 * Bz + b) * 2 + 1];
    float m1 = ml[(1 * Bz + b) * 2], l1 = ml[(1 * Bz + b) * 2 + 1];
    float m2 = ml[(2 * Bz + b) * 2], l2 = ml[(2 * Bz + b) * 2 + 1];
    float m3 = ml[(3 * Bz + b) * 2], l3 = ml[(3 * Bz + b) * 2 + 1];
    float M = fmaxf(fmaxf(m0, m1), fmaxf(m2, m3));
    float w0 = __expf(m0 - M), w1 = __expf(m1 - M);
    float w2 = __expf(m2 - M), w3 = __expf(m3 - M);
    float L = l0 * w0 + l1 * w1 + l2 * w2 + l3 * w3;
    float invL = 1.f / L;

    for (int e = tid; e < Ee; e += 256) {
        float v = ctxp[((size_t)0 * Bz + b) * Ee + e] * w0
                + ctxp[((size_t)1 * Bz + b) * Ee + e] * w1
                + ctxp[((size_t)2 * Bz + b) * Ee + e] * w2
                + ctxp[((size_t)3 * Bz + b) * Ee + e] * w3;
        cin[(size_t)b * H3 + Hh + e] = v * invL;
    }
    for (int s = tid; s < Ss; s += 256)
        aw_out[b * Ss + s] = __expf(scores[b * Ss + s] - M) * invL;
}

static float* sym(const void* s) {
    void* p = nullptr;
    cudaGetSymbolAddress(&p, s);
    return (float*)p;
}

extern "C" void kernel_launch(void* const* d_in, const int* in_sizes, int n_in,
                              void* d_out, int out_size)
{
    const int*   seq      = (const int*)  d_in[0];
    const float* h0       = (const float*)d_in[1];
    const float* c0       = (const float*)d_in[2];
    const float* enc      = (const float*)d_in[3];
    const float* emb      = (const float*)d_in[4];
    const float* w_ih     = (const float*)d_in[5];
    const float* w_hh     = (const float*)d_in[6];
    const float* b_ih     = (const float*)d_in[7];
    const float* b_hh     = (const float*)d_in[8];
    const float* attn_w   = (const float*)d_in[9];
    const float* concat_w = (const float*)d_in[11];
    const float* concat_b = (const float*)d_in[12];
    const float* out_w    = (const float*)d_in[13];
    const float* out_b    = (const float*)d_in[14];

    float* out    = (float*)d_out;
    float* h_out  = out + (size_t)Bz * Vv;
    float* c_out  = h_out + Bz * Hh;
    float* aw_out = c_out + Bz * Hh;

    float* px     = sym(g_x);
    float* ppart  = sym(g_part);
    float* psc    = sym(g_scores);
    float* pcin   = sym(g_cin);
    float* pcc    = sym(g_cc);
    float* pctxp  = sym(g_ctxp);
    float* pml    = sym(g_ml);

    // 1. embedding
    gather_k<<<(Bz * Hh) / 256, 256>>>(seq, emb, px);

    // 2. LSTM gates: both GEMMs in one launch (z: 0 = w_ih@x, 1 = w_hh@h0)
    k3_dual<<<dim3(H4 / 128, 4, 2), 256>>>(w_ih, w_hh, px, h0, ppart, H4, Hh, 8);
    lstm_pw2<<<(Bz * Hh) / 256, 256>>>(ppart, b_ih, b_hh, c0, h_out, c_out, pcin);

    // 3. attention query: q = h_new @ attn_w (attn_w is [H,E] -> BLAYOUT 1),
    //    16 split-K slices x 2 chunks = 256 CTAs; summed inside att_split
    k3_part<1><<<dim3(Ee / 128, 16), 256>>>(attn_w, h_out, ppart, Ee, Hh, 2);

    // 4. single-pass attention
    att_split<<<dim3(4, Bz), 256>>>(ppart, enc, psc, pctxp, pml);
    att_combine<<<Bz, 256>>>(pctxp, pml, psc, pcin, aw_out);

    // 5. concat GEMM + tanh (8 split-K slices x 12 chunks = 192 CTAs)
    k3_part<0><<<dim3(H3 / 128, 8), 256>>>(concat_w, pcin, ppart, H3, H3, 12);
    reduceN<8><<<(Bz * H3 / 4) / 256, 256>>>(ppart, concat_b, pcc, H3);

    // 6. vocab GEMM: direct write + bias, 250 CTAs, 2 CTAs/SM
    k3_direct<<<Vv / 128, 256>>>(out_w, pcc, out, out_b, Vv, H3, 96);
}

// round 10
// speedup vs baseline: 1.1642x; 1.1642x over previous
#include <cuda_runtime.h>
#include <cuda_bf16.h>
#include <math.h>
#include <cstdint>

// Shapes
#define Bz 64
#define Hh 1024
#define Vv 32000
#define Ss 512
#define Ee 2048   // 2H
#define H3 3072   // 3H
#define H4 4096   // 4H
#define NSPLIT 8  // attention S-splits

// ---------------- scratch ----------------
__device__ __align__(16) float g_x[Bz * Hh];
__device__ __align__(16) float g_part[8 * Bz * H4];      // 2M floats
__device__ __align__(16) float g_vpart[3 * Bz * Vv];     // vocab split-K partials
__device__ __align__(16) float g_scores[Bz * Ss];
__device__ __align__(16) float g_cin[Bz * H3];
__device__ __align__(16) float g_cc[Bz * H3];
__device__ __align__(16) float g_ctxp[NSPLIT * Bz * Ee];
__device__ __align__(16) float g_ml[NSPLIT * Bz * 2];

// ================= mma helpers =================
__device__ __forceinline__ void mma16816(float c[4],
    uint32_t a0, uint32_t a1, uint32_t a2, uint32_t a3,
    uint32_t b0, uint32_t b1)
{
    asm volatile(
        "mma.sync.aligned.m16n8k16.row.col.f32.bf16.bf16.f32 "
        "{%0,%1,%2,%3}, {%4,%5,%6,%7}, {%8,%9}, {%0,%1,%2,%3};"
        : "+f"(c[0]), "+f"(c[1]), "+f"(c[2]), "+f"(c[3])
        : "r"(a0), "r"(a1), "r"(a2), "r"(a3), "r"(b0), "r"(b1));
}

__device__ __forceinline__ void cvt4(float4 v, __nv_bfloat16* hi, __nv_bfloat16* lo)
{
    __nv_bfloat16 hx = __float2bfloat16_rn(v.x);
    __nv_bfloat16 hy = __float2bfloat16_rn(v.y);
    __nv_bfloat16 hz = __float2bfloat16_rn(v.z);
    __nv_bfloat16 hw = __float2bfloat16_rn(v.w);
    __nv_bfloat162 h01 = __halves2bfloat162(hx, hy);
    __nv_bfloat162 h23 = __halves2bfloat162(hz, hw);
    *(uint2*)hi = make_uint2(*(uint32_t*)&h01, *(uint32_t*)&h23);
    __nv_bfloat162 l01 = __halves2bfloat162(
        __float2bfloat16_rn(v.x - __bfloat162float(hx)),
        __float2bfloat16_rn(v.y - __bfloat162float(hy)));
    __nv_bfloat162 l23 = __halves2bfloat162(
        __float2bfloat16_rn(v.z - __bfloat162float(hz)),
        __float2bfloat16_rn(v.w - __bfloat162float(hw)));
    *(uint2*)lo = make_uint2(*(uint32_t*)&l01, *(uint32_t*)&l23);
}

// ================= unified 128x64 bf16 3-split GEMM body (R6 proven) =================
#define KC 32
#define GSA 40
#define GA_EL (128 * GSA)
#define GB_EL (64 * GSA)
#define G_AHI 0
#define G_ALO (2 * GA_EL)
#define G_BHI (4 * GA_EL)
#define G_BLO (4 * GA_EL + 2 * GB_EL)
#define G_SMEM_BYTES ((4 * GA_EL + 4 * GB_EL) * 2)   // 61440
#define STG_STRIDE 66

template<int BLAYOUT, int MODE>
__device__ __forceinline__ void gemm_body(
    const float* __restrict__ W, const float* __restrict__ act,
    float* __restrict__ dst, const float* __restrict__ bias,
    int N, int K, int kChunks, int n0, int kBase, __nv_bfloat16* gsm)
{
    const int tid  = threadIdx.x;
    const int lane = tid & 31;
    const int w    = tid >> 5;
    const int wm   = w & 3;
    const int wn   = w >> 2;

    float acc[2][4][4];
    #pragma unroll
    for (int i = 0; i < 2; ++i)
        #pragma unroll
        for (int j = 0; j < 4; ++j)
            #pragma unroll
            for (int q = 0; q < 4; ++q) acc[i][j][q] = 0.f;

    float4 pa[4], pbv[2];
    const int ar = tid >> 3;
    const int cg = tid & 7;

    auto loadAB = [&](int k0) {
        if (BLAYOUT == 0) {
            #pragma unroll
            for (int it = 0; it < 4; ++it)
                pa[it] = *(const float4*)&W[(size_t)(n0 + ar + it * 32) * K + k0 + cg * 4];
        } else {
            #pragma unroll
            for (int it = 0; it < 4; ++it)
                pa[it] = *(const float4*)&W[(size_t)(k0 + ar) * N + n0 + (cg + it * 8) * 4];
        }
        pbv[0] = *(const float4*)&act[(size_t)ar * K + k0 + cg * 4];
        pbv[1] = *(const float4*)&act[(size_t)(ar + 32) * K + k0 + cg * 4];
    };
    auto storeAB = [&](int buf) {
        __nv_bfloat16* AH = gsm + G_AHI + buf * GA_EL;
        __nv_bfloat16* AL = gsm + G_ALO + buf * GA_EL;
        if (BLAYOUT == 0) {
            #pragma unroll
            for (int it = 0; it < 4; ++it) {
                int m = ar + it * 32;
                cvt4(pa[it], AH + m * GSA + cg * 4, AL + m * GSA + cg * 4);
            }
        } else {
            #pragma unroll
            for (int it = 0; it < 4; ++it) {
                int ng = cg + it * 8;
                float vv[4] = { pa[it].x, pa[it].y, pa[it].z, pa[it].w };
                #pragma unroll
                for (int f = 0; f < 4; ++f) {
                    int m = ng * 4 + f;
                    __nv_bfloat16 h = __float2bfloat16_rn(vv[f]);
                    AH[m * GSA + ar] = h;
                    AL[m * GSA + ar] = __float2bfloat16_rn(vv[f] - __bfloat162float(h));
                }
            }
        }
        __nv_bfloat16* BH = gsm + G_BHI + buf * GB_EL;
        __nv_bfloat16* BL = gsm + G_BLO + buf * GB_EL;
        cvt4(pbv[0], BH + ar * GSA + cg * 4, BL + ar * GSA + cg * 4);
        cvt4(pbv[1], BH + (ar + 32) * GSA + cg * 4, BL + (ar + 32) * GSA + cg * 4);
    };

    loadAB(kBase);
    storeAB(0);
    __syncthreads();

    const int rg = lane >> 2;
    const int kq = (lane & 3) * 2;

    for (int ch = 0; ch < kChunks; ++ch) {
        const int cur = ch & 1;
        if (ch + 1 < kChunks) loadAB(kBase + (ch + 1) * KC);
        {
            const __nv_bfloat16* Ah = gsm + G_AHI + cur * GA_EL + (wm * 32) * GSA;
            const __nv_bfloat16* Al = gsm + G_ALO + cur * GA_EL + (wm * 32) * GSA;
            const __nv_bfloat16* Bh = gsm + G_BHI + cur * GB_EL + (wn * 32) * GSA;
            const __nv_bfloat16* Bl = gsm + G_BLO + cur * GB_EL + (wn * 32) * GSA;
            #pragma unroll
            for (int ks = 0; ks < KC; ks += 16) {
                const int ko = ks + kq;
                uint32_t ah[2][4], al[2][4], bh[4][2], bl[4][2];
                #pragma unroll
                for (int mt = 0; mt < 2; ++mt) {
                    const __nv_bfloat16* p = Ah + (mt * 16 + rg) * GSA + ko;
                    ah[mt][0] = *(const uint32_t*)p;
                    ah[mt][1] = *(const uint32_t*)(p + 8 * GSA);
                    ah[mt][2] = *(const uint32_t*)(p + 8);
                    ah[mt][3] = *(const uint32_t*)(p + 8 * GSA + 8);
                    const __nv_bfloat16* q = Al + (mt * 16 + rg) * GSA + ko;
                    al[mt][0] = *(const uint32_t*)q;
                    al[mt][1] = *(const uint32_t*)(q + 8 * GSA);
                    al[mt][2] = *(const uint32_t*)(q + 8);
                    al[mt][3] = *(const uint32_t*)(q + 8 * GSA + 8);
                }
                #pragma unroll
                for (int nt = 0; nt < 4; ++nt) {
                    const __nv_bfloat16* p = Bh + (nt * 8 + rg) * GSA + ko;
                    bh[nt][0] = *(const uint32_t*)p;
                    bh[nt][1] = *(const uint32_t*)(p + 8);
                    const __nv_bfloat16* q = Bl + (nt * 8 + rg) * GSA + ko;
                    bl[nt][0] = *(const uint32_t*)q;
                    bl[nt][1] = *(const uint32_t*)(q + 8);
                }
                #pragma unroll
                for (int mt = 0; mt < 2; ++mt)
                    #pragma unroll
                    for (int nt = 0; nt < 4; ++nt) {
                        mma16816(acc[mt][nt], ah[mt][0], ah[mt][1], ah[mt][2], ah[mt][3],
                                 bh[nt][0], bh[nt][1]);
                        mma16816(acc[mt][nt], ah[mt][0], ah[mt][1], ah[mt][2], ah[mt][3],
                                 bl[nt][0], bl[nt][1]);
                        mma16816(acc[mt][nt], al[mt][0], al[mt][1], al[mt][2], al[mt][3],
                                 bh[nt][0], bh[nt][1]);
                    }
            }
        }
        if (ch + 1 < kChunks) storeAB(1 - cur);
        __syncthreads();
    }

    // epilogue via smem stage
    float* stage = (float*)gsm;
    #pragma unroll
    for (int mt = 0; mt < 2; ++mt)
        #pragma unroll
        for (int nt = 0; nt < 4; ++nt) {
            int row = wm * 32 + mt * 16 + rg;
            int col = wn * 32 + nt * 8 + kq;
            *(float2*)&stage[row * STG_STRIDE + col] =
                make_float2(acc[mt][nt][0], acc[mt][nt][1]);
            *(float2*)&stage[(row + 8) * STG_STRIDE + col] =
                make_float2(acc[mt][nt][2], acc[mt][nt][3]);
        }
    __syncthreads();

    {
        const int v  = tid & 127;
        const int b0 = (tid >> 7) * 32;
        float bi = 0.f;
        if (MODE == 1) bi = bias[n0 + v];
        #pragma unroll
        for (int j = 0; j < 32; ++j) {
            int b = b0 + j;
            float val = stage[v * STG_STRIDE + b];
            if (MODE == 1)
                dst[(size_t)b * N + n0 + v] = val + bi;
            else
                dst[(size_t)b * N + n0 + v] = val;
        }
    }
}

template<int BLAYOUT>
__global__ void __launch_bounds__(256, 2) k_gemm_part(
    const float* __restrict__ W, const float* __restrict__ act,
    float* __restrict__ parts, int N, int K, int kChunks)
{
    extern __shared__ __align__(16) __nv_bfloat16 gsm[];
    gemm_body<BLAYOUT, 0>(W, act, parts + (size_t)blockIdx.y * 64 * N, nullptr,
                          N, K, kChunks, blockIdx.x * 128,
                          blockIdx.y * kChunks * KC, gsm);
}

__global__ void __launch_bounds__(256, 2) k_gemm_dual(
    const float* __restrict__ W0, const float* __restrict__ W1,
    const float* __restrict__ a0, const float* __restrict__ a1,
    float* __restrict__ parts, int N, int K, int kChunks)
{
    extern __shared__ __align__(16) __nv_bfloat16 gsm[];
    const float* W = blockIdx.z ? W1 : W0;
    const float* A = blockIdx.z ? a1 : a0;
    int slice = blockIdx.y + 4 * blockIdx.z;
    gemm_body<0, 0>(W, A, parts + (size_t)slice * 64 * N, nullptr,
                    N, K, kChunks, blockIdx.x * 128,
                    blockIdx.y * kChunks * KC, gsm);
}

// ================= reduces =================
template<int NSL>
__global__ void reduceN(const float* __restrict__ parts,
                        const float* __restrict__ b1,
                        float* __restrict__ C, int N)
{
    int i4 = blockIdx.x * 256 + threadIdx.x;
    const float4* p4 = (const float4*)parts;
    float4 s = p4[i4];
    #pragma unroll
    for (int sl = 1; sl < NSL; ++sl) {
        float4 v = p4[(size_t)sl * (64 * N / 4) + i4];
        s.x += v.x; s.y += v.y; s.z += v.z; s.w += v.w;
    }
    int n4 = i4 % (N / 4);
    float4 bv = ((const float4*)b1)[n4];
    s.x = tanhf(s.x + bv.x);
    s.y = tanhf(s.y + bv.y);
    s.z = tanhf(s.z + bv.z);
    s.w = tanhf(s.w + bv.w);
    ((float4*)C)[i4] = s;
}

__global__ void reduceV(const float* __restrict__ parts,
                        const float* __restrict__ bias,
                        float* __restrict__ out)
{
    int i4 = blockIdx.x * 256 + threadIdx.x;
    const float4* p4 = (const float4*)parts;
    float4 s = p4[i4];
    float4 v1 = p4[(size_t)1 * (Bz * Vv / 4) + i4];
    float4 v2 = p4[(size_t)2 * (Bz * Vv / 4) + i4];
    int n4 = i4 % (Vv / 4);
    float4 bv = ((const float4*)bias)[n4];
    s.x += v1.x + v2.x + bv.x;
    s.y += v1.y + v2.y + bv.y;
    s.z += v1.z + v2.z + bv.z;
    s.w += v1.w + v2.w + bv.w;
    ((float4*)out)[i4] = s;
}

// ================= pointwise =================
__global__ void gather_k(const int* __restrict__ seq, const float* __restrict__ emb,
                         float* __restrict__ x)
{
    int idx = blockIdx.x * 256 + threadIdx.x;
    int b = idx >> 10;
    x[idx] = emb[(size_t)seq[b] * Hh + (idx & 1023)];
}

__device__ __forceinline__ float sigf(float x) { return 1.f / (1.f + expf(-x)); }

__global__ void lstm_pw2(const float* __restrict__ parts,
                         const float* __restrict__ b_ih, const float* __restrict__ b_hh,
                         const float* __restrict__ c0,
                         float* __restrict__ h_out, float* __restrict__ c_out,
                         float* __restrict__ cin)
{
    int idx = blockIdx.x * 256 + threadIdx.x;   // 64*1024
    int b = idx >> 10, h = idx & 1023;
    float gate[4];
    #pragma unroll
    for (int g = 0; g < 4; ++g) {
        int n = g * Hh + h;
        float s = b_ih[n] + b_hh[n];
        #pragma unroll
        for (int sl = 0; sl < 8; ++sl)
            s += parts[(size_t)sl * 64 * H4 + (size_t)b * H4 + n];
        gate[g] = s;
    }
    float ig = sigf(gate[0]);
    float fg = sigf(gate[1]);
    float gg = tanhf(gate[2]);
    float og = sigf(gate[3]);
    float c = fg * c0[idx] + ig * gg;
    float hn = og * tanhf(c);
    c_out[idx] = c;
    h_out[idx] = hn;
    cin[(size_t)b * H3 + h] = hn;
}

// ================= single-pass split-S attention (8 splits, 4-s batched) =================
__global__ void __launch_bounds__(256) att_split(
    const float* __restrict__ qparts, const float* __restrict__ enc,
    float* __restrict__ scores, float* __restrict__ ctxp, float* __restrict__ ml)
{
    __shared__ float wsum[2][8][4];
    const int b = blockIdx.y, sp = blockIdx.x;
    const int tid = threadIdx.x, lane = tid & 31, w = tid >> 5;
    const int e0 = tid * 4;

    // q = sum of 16 split-K partial slices (N = Ee)
    float4 q0 = make_float4(0.f, 0.f, 0.f, 0.f);
    float4 q1 = make_float4(0.f, 0.f, 0.f, 0.f);
    #pragma unroll
    for (int sl = 0; sl < 16; ++sl) {
        const float* qp = qparts + (size_t)sl * 64 * Ee + (size_t)b * Ee;
        float4 a = *(const float4*)&qp[e0];
        float4 c = *(const float4*)&qp[1024 + e0];
        q0.x += a.x; q0.y += a.y; q0.z += a.z; q0.w += a.w;
        q1.x += c.x; q1.y += c.y; q1.z += c.z; q1.w += c.w;
    }

    float m = -INFINITY, l = 0.f;
    float4 c0 = make_float4(0.f, 0.f, 0.f, 0.f);
    float4 c1 = make_float4(0.f, 0.f, 0.f, 0.f);

    const int sBeg = sp * (Ss / NSPLIT);   // 64 positions per split
    const float* base = enc + (size_t)b * Ee + e0;

    float4 ce[4][2];
    #pragma unroll
    for (int j = 0; j < 4; ++j) {
        ce[j][0] = *(const float4*)&base[(size_t)(sBeg + j) * (Bz * Ee)];
        ce[j][1] = *(const float4*)&base[(size_t)(sBeg + j) * (Bz * Ee) + 1024];
    }

    for (int g = 0; g < (Ss / NSPLIT) / 4; ++g) {
        const int s0 = sBeg + g * 4;
        const int buf = g & 1;

        float d[4];
        #pragma unroll
        for (int j = 0; j < 4; ++j)
            d[j] = q0.x * ce[j][0].x + q0.y * ce[j][0].y + q0.z * ce[j][0].z + q0.w * ce[j][0].w
                 + q1.x * ce[j][1].x + q1.y * ce[j][1].y + q1.z * ce[j][1].z + q1.w * ce[j][1].w;

        float4 ne[4][2];
        if (g < (Ss / NSPLIT) / 4 - 1) {
            #pragma unroll
            for (int j = 0; j < 4; ++j) {
                ne[j][0] = *(const float4*)&base[(size_t)(s0 + 4 + j) * (Bz * Ee)];
                ne[j][1] = *(const float4*)&base[(size_t)(s0 + 4 + j) * (Bz * Ee) + 1024];
            }
        }

        #pragma unroll
        for (int o = 16; o; o >>= 1)
            #pragma unroll
            for (int j = 0; j < 4; ++j)
                d[j] += __shfl_xor_sync(0xffffffffu, d[j], o);
        if (lane < 4) wsum[buf][w][lane] = d[lane];
        __syncthreads();

        float sc[4];
        #pragma unroll
        for (int j = 0; j < 4; ++j) {
            float s = 0.f;
            #pragma unroll
            for (int ww = 0; ww < 8; ++ww) s += wsum[buf][ww][j];
            sc[j] = s;
        }
        if (tid < 4) scores[b * Ss + s0 + tid] = sc[tid];

        float mloc = fmaxf(fmaxf(sc[0], sc[1]), fmaxf(sc[2], sc[3]));
        float mn = fmaxf(m, mloc);
        float scale = __expf(m - mn);
        float pw[4];
        float psum = 0.f;
        #pragma unroll
        for (int j = 0; j < 4; ++j) { pw[j] = __expf(sc[j] - mn); psum += pw[j]; }
        l = l * scale + psum;
        c0.x = c0.x * scale; c0.y = c0.y * scale; c0.z = c0.z * scale; c0.w = c0.w * scale;
        c1.x = c1.x * scale; c1.y = c1.y * scale; c1.z = c1.z * scale; c1.w = c1.w * scale;
        #pragma unroll
        for (int j = 0; j < 4; ++j) {
            c0.x += pw[j] * ce[j][0].x; c0.y += pw[j] * ce[j][0].y;
            c0.z += pw[j] * ce[j][0].z; c0.w += pw[j] * ce[j][0].w;
            c1.x += pw[j] * ce[j][1].x; c1.y += pw[j] * ce[j][1].y;
            c1.z += pw[j] * ce[j][1].z; c1.w += pw[j] * ce[j][1].w;
        }
        m = mn;
        #pragma unroll
        for (int j = 0; j < 4; ++j) { ce[j][0] = ne[j][0]; ce[j][1] = ne[j][1]; }
    }

    float* cp = ctxp + ((size_t)sp * Bz + b) * Ee;
    *(float4*)&cp[e0] = c0;
    *(float4*)&cp[1024 + e0] = c1;
    if (tid == 0) {
        ml[(sp * Bz + b) * 2 + 0] = m;
        ml[(sp * Bz + b) * 2 + 1] = l;
    }
}

__global__ void __launch_bounds__(256) att_combine(
    const float* __restrict__ ctxp, const float* __restrict__ ml,
    const float* __restrict__ scores, float* __restrict__ cin,
    float* __restrict__ aw_out)
{
    const int b = blockIdx.x, tid = threadIdx.x;
    float ms[NSPLIT], ls[NSPLIT];
    float M = -INFINITY;
    #pragma unroll
    for (int s = 0; s < NSPLIT; ++s) {
        ms[s] = ml[(s * Bz + b) * 2 + 0];
        ls[s] = ml[(s * Bz + b) * 2 + 1];
        M = fmaxf(M, ms[s]);
    }
    float ws[NSPLIT];
    float L = 0.f;
    #pragma unroll
    for (int s = 0; s < NSPLIT; ++s) {
        ws[s] = __expf(ms[s] - M);
        L += ls[s] * ws[s];
    }
    float invL = 1.f / L;

    for (int e = tid; e < Ee; e += 256) {
        float v = 0.f;
        #pragma unroll
        for (int s = 0; s < NSPLIT; ++s)
            v += ctxp[((size_t)s * Bz + b) * Ee + e] * ws[s];
        cin[(size_t)b * H3 + Hh + e] = v * invL;
    }
    for (int s = tid; s < Ss; s += 256)
        aw_out[b * Ss + s] = __expf(scores[b * Ss + s] - M) * invL;
}

static float* sym(const void* s) {
    void* p = nullptr;
    cudaGetSymbolAddress(&p, s);
    return (float*)p;
}

extern "C" void kernel_launch(void* const* d_in, const int* in_sizes, int n_in,
                              void* d_out, int out_size)
{
    const int*   seq      = (const int*)  d_in[0];
    const float* h0       = (const float*)d_in[1];
    const float* c0       = (const float*)d_in[2];
    const float* enc      = (const float*)d_in[3];
    const float* emb      = (const float*)d_in[4];
    const float* w_ih     = (const float*)d_in[5];
    const float* w_hh     = (const float*)d_in[6];
    const float* b_ih     = (const float*)d_in[7];
    const float* b_hh     = (const float*)d_in[8];
    const float* attn_w   = (const float*)d_in[9];
    const float* concat_w = (const float*)d_in[11];
    const float* concat_b = (const float*)d_in[12];
    const float* out_w    = (const float*)d_in[13];
    const float* out_b    = (const float*)d_in[14];

    float* out    = (float*)d_out;
    float* h_out  = out + (size_t)Bz * Vv;
    float* c_out  = h_out + Bz * Hh;
    float* aw_out = c_out + Bz * Hh;

    float* px     = sym(g_x);
    float* ppart  = sym(g_part);
    float* pvpart = sym(g_vpart);
    float* psc    = sym(g_scores);
    float* pcin   = sym(g_cin);
    float* pcc    = sym(g_cc);
    float* pctxp  = sym(g_ctxp);
    float* pml    = sym(g_ml);

    cudaFuncSetAttribute(k_gemm_part<0>, cudaFuncAttributeMaxDynamicSharedMemorySize, G_SMEM_BYTES);
    cudaFuncSetAttribute(k_gemm_part<1>, cudaFuncAttributeMaxDynamicSharedMemorySize, G_SMEM_BYTES);
    cudaFuncSetAttribute(k_gemm_dual,    cudaFuncAttributeMaxDynamicSharedMemorySize, G_SMEM_BYTES);

    // 1. embedding
    gather_k<<<(Bz * Hh) / 256, 256>>>(seq, emb, px);

    // 2. LSTM gates: both GEMMs in one launch (z: 0 = w_ih@x, 1 = w_hh@h0)
    k_gemm_dual<<<dim3(H4 / 128, 4, 2), 256, G_SMEM_BYTES>>>(
        w_ih, w_hh, px, h0, ppart, H4, Hh, 8);
    lstm_pw2<<<(Bz * Hh) / 256, 256>>>(ppart, b_ih, b_hh, c0, h_out, c_out, pcin);

    // 3. attention query: q = h_new @ attn_w (attn_w is [H,E] -> BLAYOUT 1),
    //    16 split-K slices x 2 chunks = 256 CTAs; summed inside att_split
    k_gemm_part<1><<<dim3(Ee / 128, 16), 256, G_SMEM_BYTES>>>(attn_w, h_out, ppart, Ee, Hh, 2);

    // 4. single-pass attention, 8 S-splits
    att_split<<<dim3(NSPLIT, Bz), 256>>>(ppart, enc, psc, pctxp, pml);
    att_combine<<<Bz, 256>>>(pctxp, pml, psc, pcin, aw_out);

    // 5. concat GEMM + tanh (6 split-K slices x 16 chunks)
    k_gemm_part<0><<<dim3(H3 / 128, 6), 256, G_SMEM_BYTES>>>(concat_w, pcin, ppart, H3, H3, 16);
    reduceN<6><<<(Bz * H3 / 4) / 256, 256>>>(ppart, concat_b, pcc, H3);

    // 6. vocab GEMM: split-K 3 (750 CTAs), then reduce + bias
    k_gemm_part<0><<<dim3(Vv / 128, 3), 256, G_SMEM_BYTES>>>(out_w, pcc, pvpart, Vv, H3, 32);
    reduceV<<<(Bz * Vv / 4) / 256, 256>>>(pvpart, out_b, out);
}

// round 11
// speedup vs baseline: 1.2360x; 1.0617x over previous
#include <cuda_runtime.h>
#include <cuda_bf16.h>
#include <cuda_fp16.h>
#include <math.h>
#include <cstdint>

// Shapes
#define Bz 64
#define Hh 1024
#define Vv 32000
#define Ss 512
#define Ee 2048   // 2H
#define H3 3072   // 3H
#define H4 4096   // 4H
#define NSPLIT 8  // attention S-splits

// ---------------- scratch ----------------
__device__ __align__(16) float g_x[Bz * Hh];
__device__ __align__(16) float g_part[8 * Bz * H4];      // 2M floats
__device__ __align__(16) float g_vpart[3 * Bz * Vv];     // vocab split-K partials
__device__ __align__(16) float g_scores[Bz * Ss];
__device__ __align__(16) float g_cin[Bz * H3];
__device__ __align__(16) float g_cc[Bz * H3];
__device__ __align__(16) float g_ctxp[NSPLIT * Bz * Ee];
__device__ __align__(16) float g_ml[NSPLIT * Bz * 2];

// ================= mma helpers =================
__device__ __forceinline__ void mma16816(float c[4],
    uint32_t a0, uint32_t a1, uint32_t a2, uint32_t a3,
    uint32_t b0, uint32_t b1)
{
    asm volatile(
        "mma.sync.aligned.m16n8k16.row.col.f32.bf16.bf16.f32 "
        "{%0,%1,%2,%3}, {%4,%5,%6,%7}, {%8,%9}, {%0,%1,%2,%3};"
        : "+f"(c[0]), "+f"(c[1]), "+f"(c[2]), "+f"(c[3])
        : "r"(a0), "r"(a1), "r"(a2), "r"(a3), "r"(b0), "r"(b1));
}

__device__ __forceinline__ void mma16816h(float c[4],
    uint32_t a0, uint32_t a1, uint32_t a2, uint32_t a3,
    uint32_t b0, uint32_t b1)
{
    asm volatile(
        "mma.sync.aligned.m16n8k16.row.col.f32.f16.f16.f32 "
        "{%0,%1,%2,%3}, {%4,%5,%6,%7}, {%8,%9}, {%0,%1,%2,%3};"
        : "+f"(c[0]), "+f"(c[1]), "+f"(c[2]), "+f"(c[3])
        : "r"(a0), "r"(a1), "r"(a2), "r"(a3), "r"(b0), "r"(b1));
}

__device__ __forceinline__ void cvt4(float4 v, __nv_bfloat16* hi, __nv_bfloat16* lo)
{
    __nv_bfloat16 hx = __float2bfloat16_rn(v.x);
    __nv_bfloat16 hy = __float2bfloat16_rn(v.y);
    __nv_bfloat16 hz = __float2bfloat16_rn(v.z);
    __nv_bfloat16 hw = __float2bfloat16_rn(v.w);
    __nv_bfloat162 h01 = __halves2bfloat162(hx, hy);
    __nv_bfloat162 h23 = __halves2bfloat162(hz, hw);
    *(uint2*)hi = make_uint2(*(uint32_t*)&h01, *(uint32_t*)&h23);
    __nv_bfloat162 l01 = __halves2bfloat162(
        __float2bfloat16_rn(v.x - __bfloat162float(hx)),
        __float2bfloat16_rn(v.y - __bfloat162float(hy)));
    __nv_bfloat162 l23 = __halves2bfloat162(
        __float2bfloat16_rn(v.z - __bfloat162float(hz)),
        __float2bfloat16_rn(v.w - __bfloat162float(hw)));
    *(uint2*)lo = make_uint2(*(uint32_t*)&l01, *(uint32_t*)&l23);
}

// fp16 single conversion (4 floats -> 4 halves)
__device__ __forceinline__ void cvt4h(float4 v, __nv_bfloat16* hi)
{
    __half2 h01 = __floats2half2_rn(v.x, v.y);
    __half2 h23 = __floats2half2_rn(v.z, v.w);
    *(uint2*)hi = make_uint2(*(uint32_t*)&h01, *(uint32_t*)&h23);
}

// fp16 hi/lo split conversion
__device__ __forceinline__ void cvt4h2(float4 v, __nv_bfloat16* hi, __nv_bfloat16* lo)
{
    __half hx = __float2half_rn(v.x);
    __half hy = __float2half_rn(v.y);
    __half hz = __float2half_rn(v.z);
    __half hw = __float2half_rn(v.w);
    __half2 h01 = __halves2half2(hx, hy);
    __half2 h23 = __halves2half2(hz, hw);
    *(uint2*)hi = make_uint2(*(uint32_t*)&h01, *(uint32_t*)&h23);
    __half2 l01 = __floats2half2_rn(v.x - __half2float(hx), v.y - __half2float(hy));
    __half2 l23 = __floats2half2_rn(v.z - __half2float(hz), v.w - __half2float(hw));
    *(uint2*)lo = make_uint2(*(uint32_t*)&l01, *(uint32_t*)&l23);
}

// ================= unified 128x64 GEMM body =================
// PREC 0: bf16 3-split (Ah*Bh + Ah*Bl + Al*Bh), rel err ~2^-16
// PREC 1: fp16 2-term (A_single*(Bh + Bl)), rel err ~2^-11 (vocab only)
#define KC 32
#define GSA 40
#define GA_EL (128 * GSA)
#define GB_EL (64 * GSA)
#define G_AHI 0
#define G_ALO (2 * GA_EL)
#define G_BHI (4 * GA_EL)
#define G_BLO (4 * GA_EL + 2 * GB_EL)
#define G_SMEM_BYTES ((4 * GA_EL + 4 * GB_EL) * 2)   // 61440
#define STG_STRIDE 66

template<int BLAYOUT, int MODE, int PREC>
__device__ __forceinline__ void gemm_body(
    const float* __restrict__ W, const float* __restrict__ act,
    float* __restrict__ dst, const float* __restrict__ bias,
    int N, int K, int kChunks, int n0, int kBase, __nv_bfloat16* gsm)
{
    const int tid  = threadIdx.x;
    const int lane = tid & 31;
    const int w    = tid >> 5;
    const int wm   = w & 3;
    const int wn   = w >> 2;

    float acc[2][4][4];
    #pragma unroll
    for (int i = 0; i < 2; ++i)
        #pragma unroll
        for (int j = 0; j < 4; ++j)
            #pragma unroll
            for (int q = 0; q < 4; ++q) acc[i][j][q] = 0.f;

    float4 pa[4], pbv[2];
    const int ar = tid >> 3;
    const int cg = tid & 7;

    auto loadAB = [&](int k0) {
        if (BLAYOUT == 0) {
            #pragma unroll
            for (int it = 0; it < 4; ++it)
                pa[it] = *(const float4*)&W[(size_t)(n0 + ar + it * 32) * K + k0 + cg * 4];
        } else {
            #pragma unroll
            for (int it = 0; it < 4; ++it)
                pa[it] = *(const float4*)&W[(size_t)(k0 + ar) * N + n0 + (cg + it * 8) * 4];
        }
        pbv[0] = *(const float4*)&act[(size_t)ar * K + k0 + cg * 4];
        pbv[1] = *(const float4*)&act[(size_t)(ar + 32) * K + k0 + cg * 4];
    };
    auto storeAB = [&](int buf) {
        __nv_bfloat16* AH = gsm + G_AHI + buf * GA_EL;
        __nv_bfloat16* AL = gsm + G_ALO + buf * GA_EL;
        if (BLAYOUT == 0) {
            #pragma unroll
            for (int it = 0; it < 4; ++it) {
                int m = ar + it * 32;
                if (PREC == 0)
                    cvt4(pa[it], AH + m * GSA + cg * 4, AL + m * GSA + cg * 4);
                else
                    cvt4h(pa[it], AH + m * GSA + cg * 4);
            }
        } else {
            #pragma unroll
            for (int it = 0; it < 4; ++it) {
                int ng = cg + it * 8;
                float vv[4] = { pa[it].x, pa[it].y, pa[it].z, pa[it].w };
                #pragma unroll
                for (int f = 0; f < 4; ++f) {
                    int m = ng * 4 + f;
                    __nv_bfloat16 h = __float2bfloat16_rn(vv[f]);
                    AH[m * GSA + ar] = h;
                    AL[m * GSA + ar] = __float2bfloat16_rn(vv[f] - __bfloat162float(h));
                }
            }
        }
        __nv_bfloat16* BH = gsm + G_BHI + buf * GB_EL;
        __nv_bfloat16* BL = gsm + G_BLO + buf * GB_EL;
        if (PREC == 0) {
            cvt4(pbv[0], BH + ar * GSA + cg * 4, BL + ar * GSA + cg * 4);
            cvt4(pbv[1], BH + (ar + 32) * GSA + cg * 4, BL + (ar + 32) * GSA + cg * 4);
        } else {
            cvt4h2(pbv[0], BH + ar * GSA + cg * 4, BL + ar * GSA + cg * 4);
            cvt4h2(pbv[1], BH + (ar + 32) * GSA + cg * 4, BL + (ar + 32) * GSA + cg * 4);
        }
    };

    loadAB(kBase);
    storeAB(0);
    __syncthreads();

    const int rg = lane >> 2;
    const int kq = (lane & 3) * 2;

    for (int ch = 0; ch < kChunks; ++ch) {
        const int cur = ch & 1;
        if (ch + 1 < kChunks) loadAB(kBase + (ch + 1) * KC);
        {
            const __nv_bfloat16* Ah = gsm + G_AHI + cur * GA_EL + (wm * 32) * GSA;
            const __nv_bfloat16* Al = gsm + G_ALO + cur * GA_EL + (wm * 32) * GSA;
            const __nv_bfloat16* Bh = gsm + G_BHI + cur * GB_EL + (wn * 32) * GSA;
            const __nv_bfloat16* Bl = gsm + G_BLO + cur * GB_EL + (wn * 32) * GSA;
            #pragma unroll
            for (int ks = 0; ks < KC; ks += 16) {
                const int ko = ks + kq;
                uint32_t ah[2][4], al[2][4], bh[4][2], bl[4][2];
                #pragma unroll
                for (int mt = 0; mt < 2; ++mt) {
                    const __nv_bfloat16* p = Ah + (mt * 16 + rg) * GSA + ko;
                    ah[mt][0] = *(const uint32_t*)p;
                    ah[mt][1] = *(const uint32_t*)(p + 8 * GSA);
                    ah[mt][2] = *(const uint32_t*)(p + 8);
                    ah[mt][3] = *(const uint32_t*)(p + 8 * GSA + 8);
                    if (PREC == 0) {
                        const __nv_bfloat16* q = Al + (mt * 16 + rg) * GSA + ko;
                        al[mt][0] = *(const uint32_t*)q;
                        al[mt][1] = *(const uint32_t*)(q + 8 * GSA);
                        al[mt][2] = *(const uint32_t*)(q + 8);
                        al[mt][3] = *(const uint32_t*)(q + 8 * GSA + 8);
                    }
                }
                #pragma unroll
                for (int nt = 0; nt < 4; ++nt) {
                    const __nv_bfloat16* p = Bh + (nt * 8 + rg) * GSA + ko;
                    bh[nt][0] = *(const uint32_t*)p;
                    bh[nt][1] = *(const uint32_t*)(p + 8);
                    const __nv_bfloat16* q = Bl + (nt * 8 + rg) * GSA + ko;
                    bl[nt][0] = *(const uint32_t*)q;
                    bl[nt][1] = *(const uint32_t*)(q + 8);
                }
                #pragma unroll
                for (int mt = 0; mt < 2; ++mt)
                    #pragma unroll
                    for (int nt = 0; nt < 4; ++nt) {
                        if (PREC == 0) {
                            mma16816(acc[mt][nt], ah[mt][0], ah[mt][1], ah[mt][2], ah[mt][3],
                                     bh[nt][0], bh[nt][1]);
                            mma16816(acc[mt][nt], ah[mt][0], ah[mt][1], ah[mt][2], ah[mt][3],
                                     bl[nt][0], bl[nt][1]);
                            mma16816(acc[mt][nt], al[mt][0], al[mt][1], al[mt][2], al[mt][3],
                                     bh[nt][0], bh[nt][1]);
                        } else {
                            mma16816h(acc[mt][nt], ah[mt][0], ah[mt][1], ah[mt][2], ah[mt][3],
                                      bh[nt][0], bh[nt][1]);
                            mma16816h(acc[mt][nt], ah[mt][0], ah[mt][1], ah[mt][2], ah[mt][3],
                                      bl[nt][0], bl[nt][1]);
                        }
                    }
            }
        }
        if (ch + 1 < kChunks) storeAB(1 - cur);
        __syncthreads();
    }

    // epilogue via smem stage
    float* stage = (float*)gsm;
    #pragma unroll
    for (int mt = 0; mt < 2; ++mt)
        #pragma unroll
        for (int nt = 0; nt < 4; ++nt) {
            int row = wm * 32 + mt * 16 + rg;
            int col = wn * 32 + nt * 8 + kq;
            *(float2*)&stage[row * STG_STRIDE + col] =
                make_float2(acc[mt][nt][0], acc[mt][nt][1]);
            *(float2*)&stage[(row + 8) * STG_STRIDE + col] =
                make_float2(acc[mt][nt][2], acc[mt][nt][3]);
        }
    __syncthreads();

    {
        const int v  = tid & 127;
        const int b0 = (tid >> 7) * 32;
        float bi = 0.f;
        if (MODE == 1) bi = bias[n0 + v];
        #pragma unroll
        for (int j = 0; j < 32; ++j) {
            int b = b0 + j;
            float val = stage[v * STG_STRIDE + b];
            if (MODE == 1)
                dst[(size_t)b * N + n0 + v] = val + bi;
            else
                dst[(size_t)b * N + n0 + v] = val;
        }
    }
}

template<int BLAYOUT>
__global__ void __launch_bounds__(256, 2) k_gemm_part(
    const float* __restrict__ W, const float* __restrict__ act,
    float* __restrict__ parts, int N, int K, int kChunks)
{
    extern __shared__ __align__(16) __nv_bfloat16 gsm[];
    gemm_body<BLAYOUT, 0, 0>(W, act, parts + (size_t)blockIdx.y * 64 * N, nullptr,
                             N, K, kChunks, blockIdx.x * 128,
                             blockIdx.y * kChunks * KC, gsm);
}

// vocab: fp16 2-term
__global__ void __launch_bounds__(256, 2) k_gemm_vocab(
    const float* __restrict__ W, const float* __restrict__ act,
    float* __restrict__ parts, int N, int K, int kChunks)
{
    extern __shared__ __align__(16) __nv_bfloat16 gsm[];
    gemm_body<0, 0, 1>(W, act, parts + (size_t)blockIdx.y * 64 * N, nullptr,
                       N, K, kChunks, blockIdx.x * 128,
                       blockIdx.y * kChunks * KC, gsm);
}

__global__ void __launch_bounds__(256, 2) k_gemm_dual(
    const float* __restrict__ W0, const float* __restrict__ W1,
    const float* __restrict__ a0, const float* __restrict__ a1,
    float* __restrict__ parts, int N, int K, int kChunks)
{
    extern __shared__ __align__(16) __nv_bfloat16 gsm[];
    const float* W = blockIdx.z ? W1 : W0;
    const float* A = blockIdx.z ? a1 : a0;
    int slice = blockIdx.y + 4 * blockIdx.z;
    gemm_body<0, 0, 0>(W, A, parts + (size_t)slice * 64 * N, nullptr,
                       N, K, kChunks, blockIdx.x * 128,
                       blockIdx.y * kChunks * KC, gsm);
}

// ================= reduces =================
template<int NSL>
__global__ void reduceN(const float* __restrict__ parts,
                        const float* __restrict__ b1,
                        float* __restrict__ C, int N)
{
    int i4 = blockIdx.x * 256 + threadIdx.x;
    const float4* p4 = (const float4*)parts;
    float4 s = p4[i4];
    #pragma unroll
    for (int sl = 1; sl < NSL; ++sl) {
        float4 v = p4[(size_t)sl * (64 * N / 4) + i4];
        s.x += v.x; s.y += v.y; s.z += v.z; s.w += v.w;
    }
    int n4 = i4 % (N / 4);
    float4 bv = ((const float4*)b1)[n4];
    s.x = tanhf(s.x + bv.x);
    s.y = tanhf(s.y + bv.y);
    s.z = tanhf(s.z + bv.z);
    s.w = tanhf(s.w + bv.w);
    ((float4*)C)[i4] = s;
}

__global__ void reduceV(const float* __restrict__ parts,
                        const float* __restrict__ bias,
                        float* __restrict__ out)
{
    int i4 = blockIdx.x * 256 + threadIdx.x;
    const float4* p4 = (const float4*)parts;
    float4 s = p4[i4];
    float4 v1 = p4[(size_t)1 * (Bz * Vv / 4) + i4];
    float4 v2 = p4[(size_t)2 * (Bz * Vv / 4) + i4];
    int n4 = i4 % (Vv / 4);
    float4 bv = ((const float4*)bias)[n4];
    s.x += v1.x + v2.x + bv.x;
    s.y += v1.y + v2.y + bv.y;
    s.z += v1.z + v2.z + bv.z;
    s.w += v1.w + v2.w + bv.w;
    ((float4*)out)[i4] = s;
}

// ================= pointwise =================
__global__ void gather_k(const int* __restrict__ seq, const float* __restrict__ emb,
                         float* __restrict__ x)
{
    int idx = blockIdx.x * 256 + threadIdx.x;
    int b = idx >> 10;
    x[idx] = emb[(size_t)seq[b] * Hh + (idx & 1023)];
}

__device__ __forceinline__ float sigf(float x) { return 1.f / (1.f + expf(-x)); }

__global__ void lstm_pw2(const float* __restrict__ parts,
                         const float* __restrict__ b_ih, const float* __restrict__ b_hh,
                         const float* __restrict__ c0,
                         float* __restrict__ h_out, float* __restrict__ c_out,
                         float* __restrict__ cin)
{
    int idx = blockIdx.x * 256 + threadIdx.x;   // 64*1024
    int b = idx >> 10, h = idx & 1023;
    float gate[4];
    #pragma unroll
    for (int g = 0; g < 4; ++g) {
        int n = g * Hh + h;
        float s = b_ih[n] + b_hh[n];
        #pragma unroll
        for (int sl = 0; sl < 8; ++sl)
            s += parts[(size_t)sl * 64 * H4 + (size_t)b * H4 + n];
        gate[g] = s;
    }
    float ig = sigf(gate[0]);
    float fg = sigf(gate[1]);
    float gg = tanhf(gate[2]);
    float og = sigf(gate[3]);
    float c = fg * c0[idx] + ig * gg;
    float hn = og * tanhf(c);
    c_out[idx] = c;
    h_out[idx] = hn;
    cin[(size_t)b * H3 + h] = hn;
}

// ================= single-pass split-S attention (8 splits, 4-s batched) =================
__global__ void __launch_bounds__(256) att_split(
    const float* __restrict__ qparts, const float* __restrict__ enc,
    float* __restrict__ scores, float* __restrict__ ctxp, float* __restrict__ ml)
{
    __shared__ float wsum[2][8][4];
    const int b = blockIdx.y, sp = blockIdx.x;
    const int tid = threadIdx.x, lane = tid & 31, w = tid >> 5;
    const int e0 = tid * 4;

    // q = sum of 16 split-K partial slices (N = Ee)
    float4 q0 = make_float4(0.f, 0.f, 0.f, 0.f);
    float4 q1 = make_float4(0.f, 0.f, 0.f, 0.f);
    #pragma unroll
    for (int sl = 0; sl < 16; ++sl) {
        const float* qp = qparts + (size_t)sl * 64 * Ee + (size_t)b * Ee;
        float4 a = *(const float4*)&qp[e0];
        float4 c = *(const float4*)&qp[1024 + e0];
        q0.x += a.x; q0.y += a.y; q0.z += a.z; q0.w += a.w;
        q1.x += c.x; q1.y += c.y; q1.z += c.z; q1.w += c.w;
    }

    float m = -INFINITY, l = 0.f;
    float4 c0 = make_float4(0.f, 0.f, 0.f, 0.f);
    float4 c1 = make_float4(0.f, 0.f, 0.f, 0.f);

    const int sBeg = sp * (Ss / NSPLIT);   // 64 positions per split
    const float* base = enc + (size_t)b * Ee + e0;

    float4 ce[4][2];
    #pragma unroll
    for (int j = 0; j < 4; ++j) {
        ce[j][0] = *(const float4*)&base[(size_t)(sBeg + j) * (Bz * Ee)];
        ce[j][1] = *(const float4*)&base[(size_t)(sBeg + j) * (Bz * Ee) + 1024];
    }

    for (int g = 0; g < (Ss / NSPLIT) / 4; ++g) {
        const int s0 = sBeg + g * 4;
        const int buf = g & 1;

        float d[4];
        #pragma unroll
        for (int j = 0; j < 4; ++j)
            d[j] = q0.x * ce[j][0].x + q0.y * ce[j][0].y + q0.z * ce[j][0].z + q0.w * ce[j][0].w
                 + q1.x * ce[j][1].x + q1.y * ce[j][1].y + q1.z * ce[j][1].z + q1.w * ce[j][1].w;

        float4 ne[4][2];
        if (g < (Ss / NSPLIT) / 4 - 1) {
            #pragma unroll
            for (int j = 0; j < 4; ++j) {
                ne[j][0] = *(const float4*)&base[(size_t)(s0 + 4 + j) * (Bz * Ee)];
                ne[j][1] = *(const float4*)&base[(size_t)(s0 + 4 + j) * (Bz * Ee) + 1024];
            }
        }

        #pragma unroll
        for (int o = 16; o; o >>= 1)
            #pragma unroll
            for (int j = 0; j < 4; ++j)
                d[j] += __shfl_xor_sync(0xffffffffu, d[j], o);
        if (lane < 4) wsum[buf][w][lane] = d[lane];
        __syncthreads();

        float sc[4];
        #pragma unroll
        for (int j = 0; j < 4; ++j) {
            float s = 0.f;
            #pragma unroll
            for (int ww = 0; ww < 8; ++ww) s += wsum[buf][ww][j];
            sc[j] = s;
        }
        if (tid < 4) scores[b * Ss + s0 + tid] = sc[tid];

        float mloc = fmaxf(fmaxf(sc[0], sc[1]), fmaxf(sc[2], sc[3]));
        float mn = fmaxf(m, mloc);
        float scale = __expf(m - mn);
        float pw[4];
        float psum = 0.f;
        #pragma unroll
        for (int j = 0; j < 4; ++j) { pw[j] = __expf(sc[j] - mn); psum += pw[j]; }
        l = l * scale + psum;
        c0.x = c0.x * scale; c0.y = c0.y * scale; c0.z = c0.z * scale; c0.w = c0.w * scale;
        c1.x = c1.x * scale; c1.y = c1.y * scale; c1.z = c1.z * scale; c1.w = c1.w * scale;
        #pragma unroll
        for (int j = 0; j < 4; ++j) {
            c0.x += pw[j] * ce[j][0].x; c0.y += pw[j] * ce[j][0].y;
            c0.z += pw[j] * ce[j][0].z; c0.w += pw[j] * ce[j][0].w;
            c1.x += pw[j] * ce[j][1].x; c1.y += pw[j] * ce[j][1].y;
            c1.w += pw[j] * ce[j][1].w; c1.z += pw[j] * ce[j][1].z;
        }
        m = mn;
        #pragma unroll
        for (int j = 0; j < 4; ++j) { ce[j][0] = ne[j][0]; ce[j][1] = ne[j][1]; }
    }

    float* cp = ctxp + ((size_t)sp * Bz + b) * Ee;
    *(float4*)&cp[e0] = c0;
    *(float4*)&cp[1024 + e0] = c1;
    if (tid == 0) {
        ml[(sp * Bz + b) * 2 + 0] = m;
        ml[(sp * Bz + b) * 2 + 1] = l;
    }
}

__global__ void __launch_bounds__(256) att_combine(
    const float* __restrict__ ctxp, const float* __restrict__ ml,
    const float* __restrict__ scores, float* __restrict__ cin,
    float* __restrict__ aw_out)
{
    const int b = blockIdx.x, tid = threadIdx.x;
    float ms[NSPLIT], ls[NSPLIT];
    float M = -INFINITY;
    #pragma unroll
    for (int s = 0; s < NSPLIT; ++s) {
        ms[s] = ml[(s * Bz + b) * 2 + 0];
        ls[s] = ml[(s * Bz + b) * 2 + 1];
        M = fmaxf(M, ms[s]);
    }
    float ws[NSPLIT];
    float L = 0.f;
    #pragma unroll
    for (int s = 0; s < NSPLIT; ++s) {
        ws[s] = __expf(ms[s] - M);
        L += ls[s] * ws[s];
    }
    float invL = 1.f / L;

    for (int e = tid; e < Ee; e += 256) {
        float v = 0.f;
        #pragma unroll
        for (int s = 0; s < NSPLIT; ++s)
            v += ctxp[((size_t)s * Bz + b) * Ee + e] * ws[s];
        cin[(size_t)b * H3 + Hh + e] = v * invL;
    }
    for (int s = tid; s < Ss; s += 256)
        aw_out[b * Ss + s] = __expf(scores[b * Ss + s] - M) * invL;
}

static float* sym(const void* s) {
    void* p = nullptr;
    cudaGetSymbolAddress(&p, s);
    return (float*)p;
}

extern "C" void kernel_launch(void* const* d_in, const int* in_sizes, int n_in,
                              void* d_out, int out_size)
{
    const int*   seq      = (const int*)  d_in[0];
    const float* h0       = (const float*)d_in[1];
    const float* c0       = (const float*)d_in[2];
    const float* enc      = (const float*)d_in[3];
    const float* emb      = (const float*)d_in[4];
    const float* w_ih     = (const float*)d_in[5];
    const float* w_hh     = (const float*)d_in[6];
    const float* b_ih     = (const float*)d_in[7];
    const float* b_hh     = (const float*)d_in[8];
    const float* attn_w   = (const float*)d_in[9];
    const float* concat_w = (const float*)d_in[11];
    const float* concat_b = (const float*)d_in[12];
    const float* out_w    = (const float*)d_in[13];
    const float* out_b    = (const float*)d_in[14];

    float* out    = (float*)d_out;
    float* h_out  = out + (size_t)Bz * Vv;
    float* c_out  = h_out + Bz * Hh;
    float* aw_out = c_out + Bz * Hh;

    float* px     = sym(g_x);
    float* ppart  = sym(g_part);
    float* pvpart = sym(g_vpart);
    float* psc    = sym(g_scores);
    float* pcin   = sym(g_cin);
    float* pcc    = sym(g_cc);
    float* pctxp  = sym(g_ctxp);
    float* pml    = sym(g_ml);

    cudaFuncSetAttribute(k_gemm_part<0>, cudaFuncAttributeMaxDynamicSharedMemorySize, G_SMEM_BYTES);
    cudaFuncSetAttribute(k_gemm_part<1>, cudaFuncAttributeMaxDynamicSharedMemorySize, G_SMEM_BYTES);
    cudaFuncSetAttribute(k_gemm_dual,    cudaFuncAttributeMaxDynamicSharedMemorySize, G_SMEM_BYTES);
    cudaFuncSetAttribute(k_gemm_vocab,   cudaFuncAttributeMaxDynamicSharedMemorySize, G_SMEM_BYTES);

    // 1. embedding
    gather_k<<<(Bz * Hh) / 256, 256>>>(seq, emb, px);

    // 2. LSTM gates: both GEMMs in one launch (z: 0 = w_ih@x, 1 = w_hh@h0)
    k_gemm_dual<<<dim3(H4 / 128, 4, 2), 256, G_SMEM_BYTES>>>(
        w_ih, w_hh, px, h0, ppart, H4, Hh, 8);
    lstm_pw2<<<(Bz * Hh) / 256, 256>>>(ppart, b_ih, b_hh, c0, h_out, c_out, pcin);

    // 3. attention query: q = h_new @ attn_w (attn_w is [H,E] -> BLAYOUT 1),
    //    16 split-K slices x 2 chunks = 256 CTAs; summed inside att_split
    k_gemm_part<1><<<dim3(Ee / 128, 16), 256, G_SMEM_BYTES>>>(attn_w, h_out, ppart, Ee, Hh, 2);

    // 4. single-pass attention, 8 S-splits
    att_split<<<dim3(NSPLIT, Bz), 256>>>(ppart, enc, psc, pctxp, pml);
    att_combine<<<Bz, 256>>>(pctxp, pml, psc, pcin, aw_out);

    // 5. concat GEMM + tanh (6 split-K slices x 16 chunks)
    k_gemm_part<0><<<dim3(H3 / 128, 6), 256, G_SMEM_BYTES>>>(concat_w, pcin, ppart, H3, H3, 16);
    reduceN<6><<<(Bz * H3 / 4) / 256, 256>>>(ppart, concat_b, pcc, H3);

    // 6. vocab GEMM: fp16 2-term split, split-K 3 (750 CTAs), then reduce + bias
    k_gemm_vocab<<<dim3(Vv / 128, 3), 256, G_SMEM_BYTES>>>(out_w, pcc, pvpart, Vv, H3, 32);
    reduceV<<<(Bz * Vv / 4) / 256, 256>>>(pvpart, out_b, out);
}

// round 12
// speedup vs baseline: 1.3667x; 1.1057x over previous
#include <cuda_runtime.h>
#include <cuda_bf16.h>
#include <cuda_fp16.h>
#include <math.h>
#include <cstdint>

// Shapes
#define Bz 64
#define Hh 1024
#define Vv 32000
#define Ss 512
#define Ee 2048   // 2H
#define H3 3072   // 3H
#define H4 4096   // 4H
#define NSPLIT 8  // attention S-splits

// ---------------- scratch ----------------
__device__ __align__(16) float g_x[Bz * Hh];
__device__ __align__(16) float g_part[8 * Bz * H4];      // 2M floats
__device__ __align__(16) float g_vpart[3 * Bz * Vv];     // vocab split-K partials
__device__ __align__(16) float g_scores[Bz * Ss];
__device__ __align__(16) float g_cin[Bz * H3];
__device__ __align__(16) float g_cc[Bz * H3];
__device__ __align__(16) float g_ctxp[NSPLIT * Bz * Ee];
__device__ __align__(16) float g_ml[NSPLIT * Bz * 2];

// ================= mma helpers =================
__device__ __forceinline__ void mma16816(float c[4],
    uint32_t a0, uint32_t a1, uint32_t a2, uint32_t a3,
    uint32_t b0, uint32_t b1)
{
    asm volatile(
        "mma.sync.aligned.m16n8k16.row.col.f32.bf16.bf16.f32 "
        "{%0,%1,%2,%3}, {%4,%5,%6,%7}, {%8,%9}, {%0,%1,%2,%3};"
        : "+f"(c[0]), "+f"(c[1]), "+f"(c[2]), "+f"(c[3])
        : "r"(a0), "r"(a1), "r"(a2), "r"(a3), "r"(b0), "r"(b1));
}

__device__ __forceinline__ void mma16816h(float c[4],
    uint32_t a0, uint32_t a1, uint32_t a2, uint32_t a3,
    uint32_t b0, uint32_t b1)
{
    asm volatile(
        "mma.sync.aligned.m16n8k16.row.col.f32.f16.f16.f32 "
        "{%0,%1,%2,%3}, {%4,%5,%6,%7}, {%8,%9}, {%0,%1,%2,%3};"
        : "+f"(c[0]), "+f"(c[1]), "+f"(c[2]), "+f"(c[3])
        : "r"(a0), "r"(a1), "r"(a2), "r"(a3), "r"(b0), "r"(b1));
}

__device__ __forceinline__ void cvt4(float4 v, __nv_bfloat16* hi, __nv_bfloat16* lo)
{
    __nv_bfloat16 hx = __float2bfloat16_rn(v.x);
    __nv_bfloat16 hy = __float2bfloat16_rn(v.y);
    __nv_bfloat16 hz = __float2bfloat16_rn(v.z);
    __nv_bfloat16 hw = __float2bfloat16_rn(v.w);
    __nv_bfloat162 h01 = __halves2bfloat162(hx, hy);
    __nv_bfloat162 h23 = __halves2bfloat162(hz, hw);
    *(uint2*)hi = make_uint2(*(uint32_t*)&h01, *(uint32_t*)&h23);
    __nv_bfloat162 l01 = __halves2bfloat162(
        __float2bfloat16_rn(v.x - __bfloat162float(hx)),
        __float2bfloat16_rn(v.y - __bfloat162float(hy)));
    __nv_bfloat162 l23 = __halves2bfloat162(
        __float2bfloat16_rn(v.z - __bfloat162float(hz)),
        __float2bfloat16_rn(v.w - __bfloat162float(hw)));
    *(uint2*)lo = make_uint2(*(uint32_t*)&l01, *(uint32_t*)&l23);
}

// fp16 single conversion (4 floats -> 4 halves)
__device__ __forceinline__ void cvt4h(float4 v, __nv_bfloat16* hi)
{
    __half2 h01 = __floats2half2_rn(v.x, v.y);
    __half2 h23 = __floats2half2_rn(v.z, v.w);
    *(uint2*)hi = make_uint2(*(uint32_t*)&h01, *(uint32_t*)&h23);
}

// ================= unified 128x64 GEMM body =================
// PREC 0: bf16 3-split (Ah*Bh + Ah*Bl + Al*Bh), rel err ~2^-16
// PREC 1: fp16 single x single (1 mma per k16), rel err ~2^-10.5 (vocab only)
#define KC 32
#define GSA 40
#define GA_EL (128 * GSA)
#define GB_EL (64 * GSA)
#define G_AHI 0
#define G_ALO (2 * GA_EL)
#define G_BHI (4 * GA_EL)
#define G_BLO (4 * GA_EL + 2 * GB_EL)
#define G_SMEM_BYTES ((4 * GA_EL + 4 * GB_EL) * 2)   // 61440
#define STG_STRIDE 66

template<int BLAYOUT, int MODE, int PREC>
__device__ __forceinline__ void gemm_body(
    const float* __restrict__ W, const float* __restrict__ act,
    float* __restrict__ dst, const float* __restrict__ bias,
    int N, int K, int kChunks, int n0, int kBase, __nv_bfloat16* gsm)
{
    const int tid  = threadIdx.x;
    const int lane = tid & 31;
    const int w    = tid >> 5;
    const int wm   = w & 3;
    const int wn   = w >> 2;

    float acc[2][4][4];
    #pragma unroll
    for (int i = 0; i < 2; ++i)
        #pragma unroll
        for (int j = 0; j < 4; ++j)
            #pragma unroll
            for (int q = 0; q < 4; ++q) acc[i][j][q] = 0.f;

    float4 pa[4], pbv[2];
    const int ar = tid >> 3;
    const int cg = tid & 7;

    auto loadAB = [&](int k0) {
        if (BLAYOUT == 0) {
            #pragma unroll
            for (int it = 0; it < 4; ++it)
                pa[it] = *(const float4*)&W[(size_t)(n0 + ar + it * 32) * K + k0 + cg * 4];
        } else {
            #pragma unroll
            for (int it = 0; it < 4; ++it)
                pa[it] = *(const float4*)&W[(size_t)(k0 + ar) * N + n0 + (cg + it * 8) * 4];
        }
        pbv[0] = *(const float4*)&act[(size_t)ar * K + k0 + cg * 4];
        pbv[1] = *(const float4*)&act[(size_t)(ar + 32) * K + k0 + cg * 4];
    };
    auto storeAB = [&](int buf) {
        __nv_bfloat16* AH = gsm + G_AHI + buf * GA_EL;
        __nv_bfloat16* AL = gsm + G_ALO + buf * GA_EL;
        if (BLAYOUT == 0) {
            #pragma unroll
            for (int it = 0; it < 4; ++it) {
                int m = ar + it * 32;
                if (PREC == 0)
                    cvt4(pa[it], AH + m * GSA + cg * 4, AL + m * GSA + cg * 4);
                else
                    cvt4h(pa[it], AH + m * GSA + cg * 4);
            }
        } else {
            #pragma unroll
            for (int it = 0; it < 4; ++it) {
                int ng = cg + it * 8;
                float vv[4] = { pa[it].x, pa[it].y, pa[it].z, pa[it].w };
                #pragma unroll
                for (int f = 0; f < 4; ++f) {
                    int m = ng * 4 + f;
                    __nv_bfloat16 h = __float2bfloat16_rn(vv[f]);
                    AH[m * GSA + ar] = h;
                    AL[m * GSA + ar] = __float2bfloat16_rn(vv[f] - __bfloat162float(h));
                }
            }
        }
        __nv_bfloat16* BH = gsm + G_BHI + buf * GB_EL;
        __nv_bfloat16* BL = gsm + G_BLO + buf * GB_EL;
        if (PREC == 0) {
            cvt4(pbv[0], BH + ar * GSA + cg * 4, BL + ar * GSA + cg * 4);
            cvt4(pbv[1], BH + (ar + 32) * GSA + cg * 4, BL + (ar + 32) * GSA + cg * 4);
        } else {
            cvt4h(pbv[0], BH + ar * GSA + cg * 4);
            cvt4h(pbv[1], BH + (ar + 32) * GSA + cg * 4);
        }
    };

    loadAB(kBase);
    storeAB(0);
    __syncthreads();

    const int rg = lane >> 2;
    const int kq = (lane & 3) * 2;

    for (int ch = 0; ch < kChunks; ++ch) {
        const int cur = ch & 1;
        if (ch + 1 < kChunks) loadAB(kBase + (ch + 1) * KC);
        {
            const __nv_bfloat16* Ah = gsm + G_AHI + cur * GA_EL + (wm * 32) * GSA;
            const __nv_bfloat16* Al = gsm + G_ALO + cur * GA_EL + (wm * 32) * GSA;
            const __nv_bfloat16* Bh = gsm + G_BHI + cur * GB_EL + (wn * 32) * GSA;
            const __nv_bfloat16* Bl = gsm + G_BLO + cur * GB_EL + (wn * 32) * GSA;
            #pragma unroll
            for (int ks = 0; ks < KC; ks += 16) {
                const int ko = ks + kq;
                uint32_t ah[2][4], al[2][4], bh[4][2], bl[4][2];
                #pragma unroll
                for (int mt = 0; mt < 2; ++mt) {
                    const __nv_bfloat16* p = Ah + (mt * 16 + rg) * GSA + ko;
                    ah[mt][0] = *(const uint32_t*)p;
                    ah[mt][1] = *(const uint32_t*)(p + 8 * GSA);
                    ah[mt][2] = *(const uint32_t*)(p + 8);
                    ah[mt][3] = *(const uint32_t*)(p + 8 * GSA + 8);
                    if (PREC == 0) {
                        const __nv_bfloat16* q = Al + (mt * 16 + rg) * GSA + ko;
                        al[mt][0] = *(const uint32_t*)q;
                        al[mt][1] = *(const uint32_t*)(q + 8 * GSA);
                        al[mt][2] = *(const uint32_t*)(q + 8);
                        al[mt][3] = *(const uint32_t*)(q + 8 * GSA + 8);
                    }
                }
                #pragma unroll
                for (int nt = 0; nt < 4; ++nt) {
                    const __nv_bfloat16* p = Bh + (nt * 8 + rg) * GSA + ko;
                    bh[nt][0] = *(const uint32_t*)p;
                    bh[nt][1] = *(const uint32_t*)(p + 8);
                    if (PREC == 0) {
                        const __nv_bfloat16* q = Bl + (nt * 8 + rg) * GSA + ko;
                        bl[nt][0] = *(const uint32_t*)q;
                        bl[nt][1] = *(const uint32_t*)(q + 8);
                    }
                }
                #pragma unroll
                for (int mt = 0; mt < 2; ++mt)
                    #pragma unroll
                    for (int nt = 0; nt < 4; ++nt) {
                        if (PREC == 0) {
                            mma16816(acc[mt][nt], ah[mt][0], ah[mt][1], ah[mt][2], ah[mt][3],
                                     bh[nt][0], bh[nt][1]);
                            mma16816(acc[mt][nt], ah[mt][0], ah[mt][1], ah[mt][2], ah[mt][3],
                                     bl[nt][0], bl[nt][1]);
                            mma16816(acc[mt][nt], al[mt][0], al[mt][1], al[mt][2], al[mt][3],
                                     bh[nt][0], bh[nt][1]);
                        } else {
                            mma16816h(acc[mt][nt], ah[mt][0], ah[mt][1], ah[mt][2], ah[mt][3],
                                      bh[nt][0], bh[nt][1]);
                        }
                    }
            }
        }
        if (ch + 1 < kChunks) storeAB(1 - cur);
        __syncthreads();
    }

    // epilogue via smem stage
    float* stage = (float*)gsm;
    #pragma unroll
    for (int mt = 0; mt < 2; ++mt)
        #pragma unroll
        for (int nt = 0; nt < 4; ++nt) {
            int row = wm * 32 + mt * 16 + rg;
            int col = wn * 32 + nt * 8 + kq;
            *(float2*)&stage[row * STG_STRIDE + col] =
                make_float2(acc[mt][nt][0], acc[mt][nt][1]);
            *(float2*)&stage[(row + 8) * STG_STRIDE + col] =
                make_float2(acc[mt][nt][2], acc[mt][nt][3]);
        }
    __syncthreads();

    {
        const int v  = tid & 127;
        const int b0 = (tid >> 7) * 32;
        float bi = 0.f;
        if (MODE == 1) bi = bias[n0 + v];
        #pragma unroll
        for (int j = 0; j < 32; ++j) {
            int b = b0 + j;
            float val = stage[v * STG_STRIDE + b];
            if (MODE == 1)
                dst[(size_t)b * N + n0 + v] = val + bi;
            else
                dst[(size_t)b * N + n0 + v] = val;
        }
    }
}

template<int BLAYOUT>
__global__ void __launch_bounds__(256, 2) k_gemm_part(
    const float* __restrict__ W, const float* __restrict__ act,
    float* __restrict__ parts, int N, int K, int kChunks)
{
    extern __shared__ __align__(16) __nv_bfloat16 gsm[];
    gemm_body<BLAYOUT, 0, 0>(W, act, parts + (size_t)blockIdx.y * 64 * N, nullptr,
                             N, K, kChunks, blockIdx.x * 128,
                             blockIdx.y * kChunks * KC, gsm);
}

// vocab: fp16 single x single, 3 CTAs/SM
__global__ void __launch_bounds__(256, 3) k_gemm_vocab(
    const float* __restrict__ W, const float* __restrict__ act,
    float* __restrict__ parts, int N, int K, int kChunks)
{
    extern __shared__ __align__(16) __nv_bfloat16 gsm[];
    gemm_body<0, 0, 1>(W, act, parts + (size_t)blockIdx.y * 64 * N, nullptr,
                       N, K, kChunks, blockIdx.x * 128,
                       blockIdx.y * kChunks * KC, gsm);
}

__global__ void __launch_bounds__(256, 2) k_gemm_dual(
    const float* __restrict__ W0, const float* __restrict__ W1,
    const float* __restrict__ a0, const float* __restrict__ a1,
    float* __restrict__ parts, int N, int K, int kChunks)
{
    extern __shared__ __align__(16) __nv_bfloat16 gsm[];
    const float* W = blockIdx.z ? W1 : W0;
    const float* A = blockIdx.z ? a1 : a0;
    int slice = blockIdx.y + 4 * blockIdx.z;
    gemm_body<0, 0, 0>(W, A, parts + (size_t)slice * 64 * N, nullptr,
                       N, K, kChunks, blockIdx.x * 128,
                       blockIdx.y * kChunks * KC, gsm);
}

// ================= reduces =================
template<int NSL>
__global__ void reduceN(const float* __restrict__ parts,
                        const float* __restrict__ b1,
                        float* __restrict__ C, int N)
{
    int i4 = blockIdx.x * 256 + threadIdx.x;
    const float4* p4 = (const float4*)parts;
    float4 s = p4[i4];
    #pragma unroll
    for (int sl = 1; sl < NSL; ++sl) {
        float4 v = p4[(size_t)sl * (64 * N / 4) + i4];
        s.x += v.x; s.y += v.y; s.z += v.z; s.w += v.w;
    }
    int n4 = i4 % (N / 4);
    float4 bv = ((const float4*)b1)[n4];
    s.x = tanhf(s.x + bv.x);
    s.y = tanhf(s.y + bv.y);
    s.z = tanhf(s.z + bv.z);
    s.w = tanhf(s.w + bv.w);
    ((float4*)C)[i4] = s;
}

__global__ void reduceV(const float* __restrict__ parts,
                        const float* __restrict__ bias,
                        float* __restrict__ out)
{
    int i4 = blockIdx.x * 256 + threadIdx.x;
    const float4* p4 = (const float4*)parts;
    float4 s = p4[i4];
    float4 v1 = p4[(size_t)1 * (Bz * Vv / 4) + i4];
    float4 v2 = p4[(size_t)2 * (Bz * Vv / 4) + i4];
    int n4 = i4 % (Vv / 4);
    float4 bv = ((const float4*)bias)[n4];
    s.x += v1.x + v2.x + bv.x;
    s.y += v1.y + v2.y + bv.y;
    s.z += v1.z + v2.z + bv.z;
    s.w += v1.w + v2.w + bv.w;
    ((float4*)out)[i4] = s;
}

// ================= pointwise =================
__global__ void gather_k(const int* __restrict__ seq, const float* __restrict__ emb,
                         float* __restrict__ x)
{
    int idx = blockIdx.x * 256 + threadIdx.x;
    int b = idx >> 10;
    x[idx] = emb[(size_t)seq[b] * Hh + (idx & 1023)];
}

__device__ __forceinline__ float sigf(float x) { return 1.f / (1.f + expf(-x)); }

__global__ void lstm_pw2(const float* __restrict__ parts,
                         const float* __restrict__ b_ih, const float* __restrict__ b_hh,
                         const float* __restrict__ c0,
                         float* __restrict__ h_out, float* __restrict__ c_out,
                         float* __restrict__ cin)
{
    int idx = blockIdx.x * 256 + threadIdx.x;   // 64*1024
    int b = idx >> 10, h = idx & 1023;
    float gate[4];
    #pragma unroll
    for (int g = 0; g < 4; ++g) {
        int n = g * Hh + h;
        float s = b_ih[n] + b_hh[n];
        #pragma unroll
        for (int sl = 0; sl < 8; ++sl)
            s += parts[(size_t)sl * 64 * H4 + (size_t)b * H4 + n];
        gate[g] = s;
    }
    float ig = sigf(gate[0]);
    float fg = sigf(gate[1]);
    float gg = tanhf(gate[2]);
    float og = sigf(gate[3]);
    float c = fg * c0[idx] + ig * gg;
    float hn = og * tanhf(c);
    c_out[idx] = c;
    h_out[idx] = hn;
    cin[(size_t)b * H3 + h] = hn;
}

// ================= single-pass split-S attention (8 splits, 4-s batched) =================
__global__ void __launch_bounds__(256) att_split(
    const float* __restrict__ qparts, const float* __restrict__ enc,
    float* __restrict__ scores, float* __restrict__ ctxp, float* __restrict__ ml)
{
    __shared__ float wsum[2][8][4];
    const int b = blockIdx.y, sp = blockIdx.x;
    const int tid = threadIdx.x, lane = tid & 31, w = tid >> 5;
    const int e0 = tid * 4;

    // q = sum of 16 split-K partial slices (N = Ee)
    float4 q0 = make_float4(0.f, 0.f, 0.f, 0.f);
    float4 q1 = make_float4(0.f, 0.f, 0.f, 0.f);
    #pragma unroll
    for (int sl = 0; sl < 16; ++sl) {
        const float* qp = qparts + (size_t)sl * 64 * Ee + (size_t)b * Ee;
        float4 a = *(const float4*)&qp[e0];
        float4 c = *(const float4*)&qp[1024 + e0];
        q0.x += a.x; q0.y += a.y; q0.z += a.z; q0.w += a.w;
        q1.x += c.x; q1.y += c.y; q1.z += c.z; q1.w += c.w;
    }

    float m = -INFINITY, l = 0.f;
    float4 c0 = make_float4(0.f, 0.f, 0.f, 0.f);
    float4 c1 = make_float4(0.f, 0.f, 0.f, 0.f);

    const int sBeg = sp * (Ss / NSPLIT);   // 64 positions per split
    const float* base = enc + (size_t)b * Ee + e0;

    float4 ce[4][2];
    #pragma unroll
    for (int j = 0; j < 4; ++j) {
        ce[j][0] = *(const float4*)&base[(size_t)(sBeg + j) * (Bz * Ee)];
        ce[j][1] = *(const float4*)&base[(size_t)(sBeg + j) * (Bz * Ee) + 1024];
    }

    for (int g = 0; g < (Ss / NSPLIT) / 4; ++g) {
        const int s0 = sBeg + g * 4;
        const int buf = g & 1;

        float d[4];
        #pragma unroll
        for (int j = 0; j < 4; ++j)
            d[j] = q0.x * ce[j][0].x + q0.y * ce[j][0].y + q0.z * ce[j][0].z + q0.w * ce[j][0].w
                 + q1.x * ce[j][1].x + q1.y * ce[j][1].y + q1.z * ce[j][1].z + q1.w * ce[j][1].w;

        float4 ne[4][2];
        if (g < (Ss / NSPLIT) / 4 - 1) {
            #pragma unroll
            for (int j = 0; j < 4; ++j) {
                ne[j][0] = *(const float4*)&base[(size_t)(s0 + 4 + j) * (Bz * Ee)];
                ne[j][1] = *(const float4*)&base[(size_t)(s0 + 4 + j) * (Bz * Ee) + 1024];
            }
        }

        #pragma unroll
        for (int o = 16; o; o >>= 1)
            #pragma unroll
            for (int j = 0; j < 4; ++j)
                d[j] += __shfl_xor_sync(0xffffffffu, d[j], o);
        if (lane < 4) wsum[buf][w][lane] = d[lane];
        __syncthreads();

        float sc[4];
        #pragma unroll
        for (int j = 0; j < 4; ++j) {
            float s = 0.f;
            #pragma unroll
            for (int ww = 0; ww < 8; ++ww) s += wsum[buf][ww][j];
            sc[j] = s;
        }
        if (tid < 4) scores[b * Ss + s0 + tid] = sc[tid];

        float mloc = fmaxf(fmaxf(sc[0], sc[1]), fmaxf(sc[2], sc[3]));
        float mn = fmaxf(m, mloc);
        float scale = __expf(m - mn);
        float pw[4];
        float psum = 0.f;
        #pragma unroll
        for (int j = 0; j < 4; ++j) { pw[j] = __expf(sc[j] - mn); psum += pw[j]; }
        l = l * scale + psum;
        c0.x = c0.x * scale; c0.y = c0.y * scale; c0.z = c0.z * scale; c0.w = c0.w * scale;
        c1.x = c1.x * scale; c1.y = c1.y * scale; c1.z = c1.z * scale; c1.w = c1.w * scale;
        #pragma unroll
        for (int j = 0; j < 4; ++j) {
            c0.x += pw[j] * ce[j][0].x; c0.y += pw[j] * ce[j][0].y;
            c0.z += pw[j] * ce[j][0].z; c0.w += pw[j] * ce[j][0].w;
            c1.x += pw[j] * ce[j][1].x; c1.y += pw[j] * ce[j][1].y;
            c1.z += pw[j] * ce[j][1].z; c1.w += pw[j] * ce[j][1].w;
        }
        m = mn;
        #pragma unroll
        for (int j = 0; j < 4; ++j) { ce[j][0] = ne[j][0]; ce[j][1] = ne[j][1]; }
    }

    float* cp = ctxp + ((size_t)sp * Bz + b) * Ee;
    *(float4*)&cp[e0] = c0;
    *(float4*)&cp[1024 + e0] = c1;
    if (tid == 0) {
        ml[(sp * Bz + b) * 2 + 0] = m;
        ml[(sp * Bz + b) * 2 + 1] = l;
    }
}

__global__ void __launch_bounds__(256) att_combine(
    const float* __restrict__ ctxp, const float* __restrict__ ml,
    const float* __restrict__ scores, float* __restrict__ cin,
    float* __restrict__ aw_out)
{
    const int b = blockIdx.x, tid = threadIdx.x;
    float ms[NSPLIT], ls[NSPLIT];
    float M = -INFINITY;
    #pragma unroll
    for (int s = 0; s < NSPLIT; ++s) {
        ms[s] = ml[(s * Bz + b) * 2 + 0];
        ls[s] = ml[(s * Bz + b) * 2 + 1];
        M = fmaxf(M, ms[s]);
    }
    float ws[NSPLIT];
    float L = 0.f;
    #pragma unroll
    for (int s = 0; s < NSPLIT; ++s) {
        ws[s] = __expf(ms[s] - M);
        L += ls[s] * ws[s];
    }
    float invL = 1.f / L;

    for (int e = tid; e < Ee; e += 256) {
        float v = 0.f;
        #pragma unroll
        for (int s = 0; s < NSPLIT; ++s)
            v += ctxp[((size_t)s * Bz + b) * Ee + e] * ws[s];
        cin[(size_t)b * H3 + Hh + e] = v * invL;
    }
    for (int s = tid; s < Ss; s += 256)
        aw_out[b * Ss + s] = __expf(scores[b * Ss + s] - M) * invL;
}

static float* sym(const void* s) {
    void* p = nullptr;
    cudaGetSymbolAddress(&p, s);
    return (float*)p;
}

extern "C" void kernel_launch(void* const* d_in, const int* in_sizes, int n_in,
                              void* d_out, int out_size)
{
    const int*   seq      = (const int*)  d_in[0];
    const float* h0       = (const float*)d_in[1];
    const float* c0       = (const float*)d_in[2];
    const float* enc      = (const float*)d_in[3];
    const float* emb      = (const float*)d_in[4];
    const float* w_ih     = (const float*)d_in[5];
    const float* w_hh     = (const float*)d_in[6];
    const float* b_ih     = (const float*)d_in[7];
    const float* b_hh     = (const float*)d_in[8];
    const float* attn_w   = (const float*)d_in[9];
    const float* concat_w = (const float*)d_in[11];
    const float* concat_b = (const float*)d_in[12];
    const float* out_w    = (const float*)d_in[13];
    const float* out_b    = (const float*)d_in[14];

    float* out    = (float*)d_out;
    float* h_out  = out + (size_t)Bz * Vv;
    float* c_out  = h_out + Bz * Hh;
    float* aw_out = c_out + Bz * Hh;

    float* px     = sym(g_x);
    float* ppart  = sym(g_part);
    float* pvpart = sym(g_vpart);
    float* psc    = sym(g_scores);
    float* pcin   = sym(g_cin);
    float* pcc    = sym(g_cc);
    float* pctxp  = sym(g_ctxp);
    float* pml    = sym(g_ml);

    cudaFuncSetAttribute(k_gemm_part<0>, cudaFuncAttributeMaxDynamicSharedMemorySize, G_SMEM_BYTES);
    cudaFuncSetAttribute(k_gemm_part<1>, cudaFuncAttributeMaxDynamicSharedMemorySize, G_SMEM_BYTES);
    cudaFuncSetAttribute(k_gemm_dual,    cudaFuncAttributeMaxDynamicSharedMemorySize, G_SMEM_BYTES);
    cudaFuncSetAttribute(k_gemm_vocab,   cudaFuncAttributeMaxDynamicSharedMemorySize, G_SMEM_BYTES);

    // 1. embedding
    gather_k<<<(Bz * Hh) / 256, 256>>>(seq, emb, px);

    // 2. LSTM gates: both GEMMs in one launch (z: 0 = w_ih@x, 1 = w_hh@h0)
    k_gemm_dual<<<dim3(H4 / 128, 4, 2), 256, G_SMEM_BYTES>>>(
        w_ih, w_hh, px, h0, ppart, H4, Hh, 8);
    lstm_pw2<<<(Bz * Hh) / 256, 256>>>(ppart, b_ih, b_hh, c0, h_out, c_out, pcin);

    // 3. attention query: q = h_new @ attn_w (attn_w is [H,E] -> BLAYOUT 1),
    //    16 split-K slices x 2 chunks = 256 CTAs; summed inside att_split
    k_gemm_part<1><<<dim3(Ee / 128, 16), 256, G_SMEM_BYTES>>>(attn_w, h_out, ppart, Ee, Hh, 2);

    // 4. single-pass attention, 8 S-splits
    att_split<<<dim3(NSPLIT, Bz), 256>>>(ppart, enc, psc, pctxp, pml);
    att_combine<<<Bz, 256>>>(pctxp, pml, psc, pcin, aw_out);

    // 5. concat GEMM + tanh (6 split-K slices x 16 chunks)
    k_gemm_part<0><<<dim3(H3 / 128, 6), 256, G_SMEM_BYTES>>>(concat_w, pcin, ppart, H3, H3, 16);
    reduceN<6><<<(Bz * H3 / 4) / 256, 256>>>(ppart, concat_b, pcc, H3);

    // 6. vocab GEMM: fp16 single x single, split-K 3 (750 CTAs), then reduce + bias
    k_gemm_vocab<<<dim3(Vv / 128, 3), 256, G_SMEM_BYTES>>>(out_w, pcc, pvpart, Vv, H3, 32);
    reduceV<<<(Bz * Vv / 4) / 256, 256>>>(pvpart, out_b, out);
}

// round 17
// speedup vs baseline: 1.4332x; 1.0487x over previous
#include <cuda_runtime.h>
#include <cuda_bf16.h>
#include <cuda_fp16.h>
#include <math.h>
#include <cstdint>

// Shapes
#define Bz 64
#define Hh 1024
#define Vv 32000
#define Ss 512
#define Ee 2048   // 2H
#define H3 3072   // 3H
#define H4 4096   // 4H
#define NSPLIT 8  // attention S-splits

// ---------------- scratch ----------------
__device__ __align__(16) float g_x[Bz * Hh];
__device__ __align__(16) float g_wt[Ee * Hh];            // transposed attn_w [E, H]
__device__ __align__(16) float g_part[8 * Bz * H4];      // 2M floats
__device__ __align__(16) float g_vpart[3 * Bz * Vv];     // vocab split-K partials
__device__ __align__(16) float g_scores[Bz * Ss];
__device__ __align__(16) float g_cin[Bz * H3];
__device__ __align__(16) float g_cc[Bz * H3];
__device__ __align__(16) float g_ctxp[NSPLIT * Bz * Ee];
__device__ __align__(16) float g_ml[NSPLIT * Bz * 2];

// ================= mma helpers =================
__device__ __forceinline__ void mma16816(float c[4],
    uint32_t a0, uint32_t a1, uint32_t a2, uint32_t a3,
    uint32_t b0, uint32_t b1)
{
    asm volatile(
        "mma.sync.aligned.m16n8k16.row.col.f32.bf16.bf16.f32 "
        "{%0,%1,%2,%3}, {%4,%5,%6,%7}, {%8,%9}, {%0,%1,%2,%3};"
        : "+f"(c[0]), "+f"(c[1]), "+f"(c[2]), "+f"(c[3])
        : "r"(a0), "r"(a1), "r"(a2), "r"(a3), "r"(b0), "r"(b1));
}

__device__ __forceinline__ void mma16816h(float c[4],
    uint32_t a0, uint32_t a1, uint32_t a2, uint32_t a3,
    uint32_t b0, uint32_t b1)
{
    asm volatile(
        "mma.sync.aligned.m16n8k16.row.col.f32.f16.f16.f32 "
        "{%0,%1,%2,%3}, {%4,%5,%6,%7}, {%8,%9}, {%0,%1,%2,%3};"
        : "+f"(c[0]), "+f"(c[1]), "+f"(c[2]), "+f"(c[3])
        : "r"(a0), "r"(a1), "r"(a2), "r"(a3), "r"(b0), "r"(b1));
}

__device__ __forceinline__ void cvt4(float4 v, __nv_bfloat16* hi, __nv_bfloat16* lo)
{
    __nv_bfloat16 hx = __float2bfloat16_rn(v.x);
    __nv_bfloat16 hy = __float2bfloat16_rn(v.y);
    __nv_bfloat16 hz = __float2bfloat16_rn(v.z);
    __nv_bfloat16 hw = __float2bfloat16_rn(v.w);
    __nv_bfloat162 h01 = __halves2bfloat162(hx, hy);
    __nv_bfloat162 h23 = __halves2bfloat162(hz, hw);
    *(uint2*)hi = make_uint2(*(uint32_t*)&h01, *(uint32_t*)&h23);
    __nv_bfloat162 l01 = __halves2bfloat162(
        __float2bfloat16_rn(v.x - __bfloat162float(hx)),
        __float2bfloat16_rn(v.y - __bfloat162float(hy)));
    __nv_bfloat162 l23 = __halves2bfloat162(
        __float2bfloat16_rn(v.z - __bfloat162float(hz)),
        __float2bfloat16_rn(v.w - __bfloat162float(hw)));
    *(uint2*)lo = make_uint2(*(uint32_t*)&l01, *(uint32_t*)&l23);
}

// fp16 single conversion (4 floats -> 4 halves), dest as raw bf16* alias
__device__ __forceinline__ void cvt4h(float4 v, __nv_bfloat16* hi)
{
    __half2 h01 = __floats2half2_rn(v.x, v.y);
    __half2 h23 = __floats2half2_rn(v.z, v.w);
    *(uint2*)hi = make_uint2(*(uint32_t*)&h01, *(uint32_t*)&h23);
}

// ================= unified 128x64 GEMM body =================
// PREC 0: bf16 3-split (Ah*Bh + Ah*Bl + Al*Bh), rel err ~2^-16
// PREC 1: fp16 single x single (1 mma per k16), rel err ~2^-10.5
#define KC 32
#define GSA 40
#define GA_EL (128 * GSA)
#define GB_EL (64 * GSA)
#define G_AHI 0
#define G_ALO (2 * GA_EL)
#define G_BHI (4 * GA_EL)
#define G_BLO (4 * GA_EL + 2 * GB_EL)
#define G_SMEM_BYTES ((4 * GA_EL + 4 * GB_EL) * 2)   // 61440
#define STG_STRIDE 66

template<int BLAYOUT, int MODE, int PREC>
__device__ __forceinline__ void gemm_body(
    const float* __restrict__ W, const float* __restrict__ act,
    float* __restrict__ dst, const float* __restrict__ bias,
    int N, int K, int kChunks, int n0, int kBase, __nv_bfloat16* gsm)
{
    const int tid  = threadIdx.x;
    const int lane = tid & 31;
    const int w    = tid >> 5;
    const int wm   = w & 3;
    const int wn   = w >> 2;

    float acc[2][4][4];
    #pragma unroll
    for (int i = 0; i < 2; ++i)
        #pragma unroll
        for (int j = 0; j < 4; ++j)
            #pragma unroll
            for (int q = 0; q < 4; ++q) acc[i][j][q] = 0.f;

    float4 pa[4], pbv[2];
    const int ar = tid >> 3;
    const int cg = tid & 7;

    auto loadAB = [&](int k0) {
        if (BLAYOUT == 0) {
            #pragma unroll
            for (int it = 0; it < 4; ++it)
                pa[it] = *(const float4*)&W[(size_t)(n0 + ar + it * 32) * K + k0 + cg * 4];
        } else {
            #pragma unroll
            for (int it = 0; it < 4; ++it)
                pa[it] = *(const float4*)&W[(size_t)(k0 + ar) * N + n0 + (cg + it * 8) * 4];
        }
        pbv[0] = *(const float4*)&act[(size_t)ar * K + k0 + cg * 4];
        pbv[1] = *(const float4*)&act[(size_t)(ar + 32) * K + k0 + cg * 4];
    };
    auto storeAB = [&](int buf) {
        __nv_bfloat16* AH = gsm + G_AHI + buf * GA_EL;
        __nv_bfloat16* AL = gsm + G_ALO + buf * GA_EL;
        if (BLAYOUT == 0) {
            #pragma unroll
            for (int it = 0; it < 4; ++it) {
                int m = ar + it * 32;
                if (PREC == 0)
                    cvt4(pa[it], AH + m * GSA + cg * 4, AL + m * GSA + cg * 4);
                else
                    cvt4h(pa[it], AH + m * GSA + cg * 4);
            }
        } else {
            #pragma unroll
            for (int it = 0; it < 4; ++it) {
                int ng = cg + it * 8;
                float vv[4] = { pa[it].x, pa[it].y, pa[it].z, pa[it].w };
                #pragma unroll
                for (int f = 0; f < 4; ++f) {
                    int m = ng * 4 + f;
                    __nv_bfloat16 h = __float2bfloat16_rn(vv[f]);
                    AH[m * GSA + ar] = h;
                    AL[m * GSA + ar] = __float2bfloat16_rn(vv[f] - __bfloat162float(h));
                }
            }
        }
        __nv_bfloat16* BH = gsm + G_BHI + buf * GB_EL;
        __nv_bfloat16* BL = gsm + G_BLO + buf * GB_EL;
        if (PREC == 0) {
            cvt4(pbv[0], BH + ar * GSA + cg * 4, BL + ar * GSA + cg * 4);
            cvt4(pbv[1], BH + (ar + 32) * GSA + cg * 4, BL + (ar + 32) * GSA + cg * 4);
        } else {
            cvt4h(pbv[0], BH + ar * GSA + cg * 4);
            cvt4h(pbv[1], BH + (ar + 32) * GSA + cg * 4);
        }
    };

    loadAB(kBase);
    storeAB(0);
    __syncthreads();

    const int rg = lane >> 2;
    const int kq = (lane & 3) * 2;

    for (int ch = 0; ch < kChunks; ++ch) {
        const int cur = ch & 1;
        if (ch + 1 < kChunks) loadAB(kBase + (ch + 1) * KC);
        {
            const __nv_bfloat16* Ah = gsm + G_AHI + cur * GA_EL + (wm * 32) * GSA;
            const __nv_bfloat16* Al = gsm + G_ALO + cur * GA_EL + (wm * 32) * GSA;
            const __nv_bfloat16* Bh = gsm + G_BHI + cur * GB_EL + (wn * 32) * GSA;
            const __nv_bfloat16* Bl = gsm + G_BLO + cur * GB_EL + (wn * 32) * GSA;
            #pragma unroll
            for (int ks = 0; ks < KC; ks += 16) {
                const int ko = ks + kq;
                uint32_t ah[2][4], al[2][4], bh[4][2], bl[4][2];
                #pragma unroll
                for (int mt = 0; mt < 2; ++mt) {
                    const __nv_bfloat16* p = Ah + (mt * 16 + rg) * GSA + ko;
                    ah[mt][0] = *(const uint32_t*)p;
                    ah[mt][1] = *(const uint32_t*)(p + 8 * GSA);
                    ah[mt][2] = *(const uint32_t*)(p + 8);
                    ah[mt][3] = *(const uint32_t*)(p + 8 * GSA + 8);
                    if (PREC == 0) {
                        const __nv_bfloat16* q = Al + (mt * 16 + rg) * GSA + ko;
                        al[mt][0] = *(const uint32_t*)q;
                        al[mt][1] = *(const uint32_t*)(q + 8 * GSA);
                        al[mt][2] = *(const uint32_t*)(q + 8);
                        al[mt][3] = *(const uint32_t*)(q + 8 * GSA + 8);
                    }
                }
                #pragma unroll
                for (int nt = 0; nt < 4; ++nt) {
                    const __nv_bfloat16* p = Bh + (nt * 8 + rg) * GSA + ko;
                    bh[nt][0] = *(const uint32_t*)p;
                    bh[nt][1] = *(const uint32_t*)(p + 8);
                    if (PREC == 0) {
                        const __nv_bfloat16* q = Bl + (nt * 8 + rg) * GSA + ko;
                        bl[nt][0] = *(const uint32_t*)q;
                        bl[nt][1] = *(const uint32_t*)(q + 8);
                    }
                }
                #pragma unroll
                for (int mt = 0; mt < 2; ++mt)
                    #pragma unroll
                    for (int nt = 0; nt < 4; ++nt) {
                        if (PREC == 0) {
                            mma16816(acc[mt][nt], ah[mt][0], ah[mt][1], ah[mt][2], ah[mt][3],
                                     bh[nt][0], bh[nt][1]);
                            mma16816(acc[mt][nt], ah[mt][0], ah[mt][1], ah[mt][2], ah[mt][3],
                                     bl[nt][0], bl[nt][1]);
                            mma16816(acc[mt][nt], al[mt][0], al[mt][1], al[mt][2], al[mt][3],
                                     bh[nt][0], bh[nt][1]);
                        } else {
                            mma16816h(acc[mt][nt], ah[mt][0], ah[mt][1], ah[mt][2], ah[mt][3],
                                      bh[nt][0], bh[nt][1]);
                        }
                    }
            }
        }
        if (ch + 1 < kChunks) storeAB(1 - cur);
        __syncthreads();
    }

    // epilogue via smem stage
    float* stage = (float*)gsm;
    #pragma unroll
    for (int mt = 0; mt < 2; ++mt)
        #pragma unroll
        for (int nt = 0; nt < 4; ++nt) {
            int row = wm * 32 + mt * 16 + rg;
            int col = wn * 32 + nt * 8 + kq;
            *(float2*)&stage[row * STG_STRIDE + col] =
                make_float2(acc[mt][nt][0], acc[mt][nt][1]);
            *(float2*)&stage[(row + 8) * STG_STRIDE + col] =
                make_float2(acc[mt][nt][2], acc[mt][nt][3]);
        }
    __syncthreads();

    {
        const int v  = tid & 127;
        const int b0 = (tid >> 7) * 32;
        float bi = 0.f;
        if (MODE == 1) bi = bias[n0 + v];
        #pragma unroll
        for (int j = 0; j < 32; ++j) {
            int b = b0 + j;
            float val = stage[v * STG_STRIDE + b];
            if (MODE == 1)
                dst[(size_t)b * N + n0 + v] = val + bi;
            else
                dst[(size_t)b * N + n0 + v] = val;
        }
    }
}

template<int BLAYOUT, int PREC>
__global__ void __launch_bounds__(256, 2) k_gemm_part(
    const float* __restrict__ W, const float* __restrict__ act,
    float* __restrict__ parts, int N, int K, int kChunks)
{
    extern __shared__ __align__(16) __nv_bfloat16 gsm[];
    gemm_body<BLAYOUT, 0, PREC>(W, act, parts + (size_t)blockIdx.y * 64 * N, nullptr,
                                N, K, kChunks, blockIdx.x * 128,
                                blockIdx.y * kChunks * KC, gsm);
}

__global__ void __launch_bounds__(256, 2) k_gemm_dual(
    const float* __restrict__ W0, const float* __restrict__ W1,
    const float* __restrict__ a0, const float* __restrict__ a1,
    float* __restrict__ parts, int N, int K, int kChunks)
{
    extern __shared__ __align__(16) __nv_bfloat16 gsm[];
    const float* W = blockIdx.z ? W1 : W0;
    const float* A = blockIdx.z ? a1 : a0;
    int slice = blockIdx.y + 4 * blockIdx.z;
    gemm_body<0, 0, 0>(W, A, parts + (size_t)slice * 64 * N, nullptr,
                       N, K, kChunks, blockIdx.x * 128,
                       blockIdx.y * kChunks * KC, gsm);
}

// ============ dedicated vocab GEMM: KC=64, fp16 single, double-buffered ============
#define KV 64
#define VSA 72
#define VA_EL (128 * VSA)   // 9216 halves
#define VB_EL (64 * VSA)    // 4608 halves
#define V_SMEM_BYTES ((2 * VA_EL + 2 * VB_EL) * 2)   // 55296 B

__global__ void __launch_bounds__(256, 2) k_vocab64(
    const float* __restrict__ W, const float* __restrict__ act,
    float* __restrict__ parts, int kChunks)
{
    extern __shared__ __align__(16) __nv_bfloat16 vsm[];
    const int tid  = threadIdx.x;
    const int lane = tid & 31;
    const int w    = tid >> 5;
    const int wm   = w & 3;
    const int wn   = w >> 2;
    const int n0   = blockIdx.x * 128;
    const int kBase = blockIdx.y * kChunks * KV;
    const int K = H3;

    float acc[2][4][4];
    #pragma unroll
    for (int i = 0; i < 2; ++i)
        #pragma unroll
        for (int j = 0; j < 4; ++j)
            #pragma unroll
            for (int q = 0; q < 4; ++q) acc[i][j][q] = 0.f;

    const int ar = tid >> 3;   // 0..31
    const int cg = tid & 7;

    float4 pa[8], pb[4];
    auto loadAB = [&](int k0) {
        #pragma unroll
        for (int it = 0; it < 4; ++it) {
            const float* p = &W[(size_t)(n0 + ar + it * 32) * K + k0 + cg * 8];
            pa[it * 2]     = *(const float4*)p;
            pa[it * 2 + 1] = *(const float4*)(p + 4);
        }
        #pragma unroll
        for (int it = 0; it < 2; ++it) {
            const float* p = &act[(size_t)(ar + it * 32) * K + k0 + cg * 8];
            pb[it * 2]     = *(const float4*)p;
            pb[it * 2 + 1] = *(const float4*)(p + 4);
        }
    };
    auto storeAB = [&](int buf) {
        __nv_bfloat16* AH = vsm + buf * VA_EL;
        #pragma unroll
        for (int it = 0; it < 4; ++it) {
            int m = ar + it * 32;
            cvt4h(pa[it * 2],     AH + m * VSA + cg * 8);
            cvt4h(pa[it * 2 + 1], AH + m * VSA + cg * 8 + 4);
        }
        __nv_bfloat16* BH = vsm + 2 * VA_EL + buf * VB_EL;
        #pragma unroll
        for (int it = 0; it < 2; ++it) {
            int m = ar + it * 32;
            cvt4h(pb[it * 2],     BH + m * VSA + cg * 8);
            cvt4h(pb[it * 2 + 1], BH + m * VSA + cg * 8 + 4);
        }
    };

    loadAB(kBase);
    storeAB(0);
    __syncthreads();

    const int rg = lane >> 2;
    const int kq = (lane & 3) * 2;

    for (int ch = 0; ch < kChunks; ++ch) {
        const int cur = ch & 1;
        if (ch + 1 < kChunks) loadAB(kBase + (ch + 1) * KV);
        {
            const __nv_bfloat16* AH = vsm + cur * VA_EL + (wm * 32) * VSA;
            const __nv_bfloat16* BH = vsm + 2 * VA_EL + cur * VB_EL + (wn * 32) * VSA;
            #pragma unroll
            for (int ks = 0; ks < 4; ++ks) {
                const int ko = ks * 16 + kq;
                uint32_t ah[2][4], bh[4][2];
                #pragma unroll
                for (int mt = 0; mt < 2; ++mt) {
                    const __nv_bfloat16* p = AH + (mt * 16 + rg) * VSA + ko;
                    ah[mt][0] = *(const uint32_t*)p;
                    ah[mt][1] = *(const uint32_t*)(p + 8 * VSA);
                    ah[mt][2] = *(const uint32_t*)(p + 8);
                    ah[mt][3] = *(const uint32_t*)(p + 8 * VSA + 8);
                }
                #pragma unroll
                for (int nt = 0; nt < 4; ++nt) {
                    const __nv_bfloat16* p = BH + (nt * 8 + rg) * VSA + ko;
                    bh[nt][0] = *(const uint32_t*)p;
                    bh[nt][1] = *(const uint32_t*)(p + 8);
                }
                #pragma unroll
                for (int mt = 0; mt < 2; ++mt)
                    #pragma unroll
                    for (int nt = 0; nt < 4; ++nt)
                        mma16816h(acc[mt][nt], ah[mt][0], ah[mt][1], ah[mt][2], ah[mt][3],
                                  bh[nt][0], bh[nt][1]);
            }
        }
        if (ch + 1 < kChunks) storeAB(1 - cur);
        __syncthreads();
    }

    // epilogue via smem stage
    float* stage = (float*)vsm;
    #pragma unroll
    for (int mt = 0; mt < 2; ++mt)
        #pragma unroll
        for (int nt = 0; nt < 4; ++nt) {
            int row = wm * 32 + mt * 16 + rg;
            int col = wn * 32 + nt * 8 + kq;
            *(float2*)&stage[row * STG_STRIDE + col] =
                make_float2(acc[mt][nt][0], acc[mt][nt][1]);
            *(float2*)&stage[(row + 8) * STG_STRIDE + col] =
                make_float2(acc[mt][nt][2], acc[mt][nt][3]);
        }
    __syncthreads();

    {
        float* dst = parts + (size_t)blockIdx.y * 64 * Vv;
        const int v  = tid & 127;
        const int b0 = (tid >> 7) * 32;
        #pragma unroll
        for (int j = 0; j < 32; ++j) {
            int b = b0 + j;
            dst[(size_t)b * Vv + n0 + v] = stage[v * STG_STRIDE + b];
        }
    }
}

// ================= attn_w transpose: [H,E] -> [E,H] =================
__global__ void transpose_w(const float* __restrict__ w, float* __restrict__ wt)
{
    __shared__ float t[32][33];
    int e0 = blockIdx.x * 32, h0 = blockIdx.y * 32;
    int tx = threadIdx.x, ty0 = threadIdx.y;
    #pragma unroll
    for (int i = 0; i < 4; ++i) {
        int ty = ty0 + i * 8;
        t[ty][tx] = w[(size_t)(h0 + ty) * Ee + e0 + tx];
    }
    __syncthreads();
    #pragma unroll
    for (int i = 0; i < 4; ++i) {
        int ty = ty0 + i * 8;
        wt[(size_t)(e0 + ty) * Hh + h0 + tx] = t[tx][ty];
    }
}

// ================= reduces =================
template<int NSL>
__global__ void reduceN(const float* __restrict__ parts,
                        const float* __restrict__ b1,
                        float* __restrict__ C, int N)
{
    int i4 = blockIdx.x * 256 + threadIdx.x;
    const float4* p4 = (const float4*)parts;
    float4 s = p4[i4];
    #pragma unroll
    for (int sl = 1; sl < NSL; ++sl) {
        float4 v = p4[(size_t)sl * (64 * N / 4) + i4];
        s.x += v.x; s.y += v.y; s.z += v.z; s.w += v.w;
    }
    int n4 = i4 % (N / 4);
    float4 bv = ((const float4*)b1)[n4];
    s.x = tanhf(s.x + bv.x);
    s.y = tanhf(s.y + bv.y);
    s.z = tanhf(s.z + bv.z);
    s.w = tanhf(s.w + bv.w);
    ((float4*)C)[i4] = s;
}

__global__ void reduceV(const float* __restrict__ parts,
                        const float* __restrict__ bias,
                        float* __restrict__ out)
{
    int i4 = blockIdx.x * 256 + threadIdx.x;
    const float4* p4 = (const float4*)parts;
    float4 s = p4[i4];
    float4 v1 = p4[(size_t)1 * (Bz * Vv / 4) + i4];
    float4 v2 = p4[(size_t)2 * (Bz * Vv / 4) + i4];
    int n4 = i4 % (Vv / 4);
    float4 bv = ((const float4*)bias)[n4];
    s.x += v1.x + v2.x + bv.x;
    s.y += v1.y + v2.y + bv.y;
    s.z += v1.z + v2.z + bv.z;
    s.w += v1.w + v2.w + bv.w;
    ((float4*)out)[i4] = s;
}

// ================= pointwise =================
__global__ void gather_k(const int* __restrict__ seq, const float* __restrict__ emb,
                         float* __restrict__ x)
{
    int idx = blockIdx.x * 256 + threadIdx.x;
    int b = idx >> 10;
    x[idx] = emb[(size_t)seq[b] * Hh + (idx & 1023)];
}

__device__ __forceinline__ float sigf(float x) { return 1.f / (1.f + expf(-x)); }

__global__ void lstm_pw2(const float* __restrict__ parts,
                         const float* __restrict__ b_ih, const float* __restrict__ b_hh,
                         const float* __restrict__ c0,
                         float* __restrict__ h_out, float* __restrict__ c_out,
                         float* __restrict__ cin)
{
    int idx = blockIdx.x * 256 + threadIdx.x;   // 64*1024
    int b = idx >> 10, h = idx & 1023;
    float gate[4];
    #pragma unroll
    for (int g = 0; g < 4; ++g) {
        int n = g * Hh + h;
        float s = b_ih[n] + b_hh[n];
        #pragma unroll
        for (int sl = 0; sl < 8; ++sl)
            s += parts[(size_t)sl * 64 * H4 + (size_t)b * H4 + n];
        gate[g] = s;
    }
    float ig = sigf(gate[0]);
    float fg = sigf(gate[1]);
    float gg = tanhf(gate[2]);
    float og = sigf(gate[3]);
    float c = fg * c0[idx] + ig * gg;
    float hn = og * tanhf(c);
    c_out[idx] = c;
    h_out[idx] = hn;
    cin[(size_t)b * H3 + h] = hn;
}

// ================= single-pass split-S attention (8 splits, 4-s batched) =================
__global__ void __launch_bounds__(256) att_split(
    const float* __restrict__ qparts, const float* __restrict__ enc,
    float* __restrict__ scores, float* __restrict__ ctxp, float* __restrict__ ml)
{
    __shared__ float wsum[2][8][4];
    const int b = blockIdx.y, sp = blockIdx.x;
    const int tid = threadIdx.x, lane = tid & 31, w = tid >> 5;
    const int e0 = tid * 4;

    // q = sum of 16 split-K partial slices (N = Ee)
    float4 q0 = make_float4(0.f, 0.f, 0.f, 0.f);
    float4 q1 = make_float4(0.f, 0.f, 0.f, 0.f);
    #pragma unroll
    for (int sl = 0; sl < 16; ++sl) {
        const float* qp = qparts + (size_t)sl * 64 * Ee + (size_t)b * Ee;
        float4 a = *(const float4*)&qp[e0];
        float4 c = *(const float4*)&qp[1024 + e0];
        q0.x += a.x; q0.y += a.y; q0.z += a.z; q0.w += a.w;
        q1.x += c.x; q1.y += c.y; q1.z += c.z; q1.w += c.w;
    }

    float m = -INFINITY, l = 0.f;
    float4 c0 = make_float4(0.f, 0.f, 0.f, 0.f);
    float4 c1 = make_float4(0.f, 0.f, 0.f, 0.f);

    const int sBeg = sp * (Ss / NSPLIT);   // 64 positions per split
    const float* base = enc + (size_t)b * Ee + e0;

    float4 ce[4][2];
    #pragma unroll
    for (int j = 0; j < 4; ++j) {
        ce[j][0] = *(const float4*)&base[(size_t)(sBeg + j) * (Bz * Ee)];
        ce[j][1] = *(const float4*)&base[(size_t)(sBeg + j) * (Bz * Ee) + 1024];
    }

    for (int g = 0; g < (Ss / NSPLIT) / 4; ++g) {
        const int s0 = sBeg + g * 4;
        const int buf = g & 1;

        float d[4];
        #pragma unroll
        for (int j = 0; j < 4; ++j)
            d[j] = q0.x * ce[j][0].x + q0.y * ce[j][0].y + q0.z * ce[j][0].z + q0.w * ce[j][0].w
                 + q1.x * ce[j][1].x + q1.y * ce[j][1].y + q1.z * ce[j][1].z + q1.w * ce[j][1].w;

        float4 ne[4][2];
        if (g < (Ss / NSPLIT) / 4 - 1) {
            #pragma unroll
            for (int j = 0; j < 4; ++j) {
                ne[j][0] = *(const float4*)&base[(size_t)(s0 + 4 + j) * (Bz * Ee)];
                ne[j][1] = *(const float4*)&base[(size_t)(s0 + 4 + j) * (Bz * Ee) + 1024];
            }
        }

        #pragma unroll
        for (int o = 16; o; o >>= 1)
            #pragma unroll
            for (int j = 0; j < 4; ++j)
                d[j] += __shfl_xor_sync(0xffffffffu, d[j], o);
        if (lane < 4) wsum[buf][w][lane] = d[lane];
        __syncthreads();

        float sc[4];
        #pragma unroll
        for (int j = 0; j < 4; ++j) {
            float s = 0.f;
            #pragma unroll
            for (int ww = 0; ww < 8; ++ww) s += wsum[buf][ww][j];
            sc[j] = s;
        }
        if (tid < 4) scores[b * Ss + s0 + tid] = sc[tid];

        float mloc = fmaxf(fmaxf(sc[0], sc[1]), fmaxf(sc[2], sc[3]));
        float mn = fmaxf(m, mloc);
        float scale = __expf(m - mn);
        float pw[4];
        float psum = 0.f;
        #pragma unroll
        for (int j = 0; j < 4; ++j) { pw[j] = __expf(sc[j] - mn); psum += pw[j]; }
        l = l * scale + psum;
        c0.x = c0.x * scale; c0.y = c0.y * scale; c0.z = c0.z * scale; c0.w = c0.w * scale;
        c1.x = c1.x * scale; c1.y = c1.y * scale; c1.z = c1.z * scale; c1.w = c1.w * scale;
        #pragma unroll
        for (int j = 0; j < 4; ++j) {
            c0.x += pw[j] * ce[j][0].x; c0.y += pw[j] * ce[j][0].y;
            c0.z += pw[j] * ce[j][0].z; c0.w += pw[j] * ce[j][0].w;
            c1.x += pw[j] * ce[j][1].x; c1.y += pw[j] * ce[j][1].y;
            c1.z += pw[j] * ce[j][1].z; c1.w += pw[j] * ce[j][1].w;
        }
        m = mn;
        #pragma unroll
        for (int j = 0; j < 4; ++j) { ce[j][0] = ne[j][0]; ce[j][1] = ne[j][1]; }
    }

    float* cp = ctxp + ((size_t)sp * Bz + b) * Ee;
    *(float4*)&cp[e0] = c0;
    *(float4*)&cp[1024 + e0] = c1;
    if (tid == 0) {
        ml[(sp * Bz + b) * 2 + 0] = m;
        ml[(sp * Bz + b) * 2 + 1] = l;
    }
}

__global__ void __launch_bounds__(256) att_combine(
    const float* __restrict__ ctxp, const float* __restrict__ ml,
    const float* __restrict__ scores, float* __restrict__ cin,
    float* __restrict__ aw_out)
{
    const int b = blockIdx.x, tid = threadIdx.x;
    float ms[NSPLIT], ls[NSPLIT];
    float M = -INFINITY;
    #pragma unroll
    for (int s = 0; s < NSPLIT; ++s) {
        ms[s] = ml[(s * Bz + b) * 2 + 0];
        ls[s] = ml[(s * Bz + b) * 2 + 1];
        M = fmaxf(M, ms[s]);
    }
    float ws[NSPLIT];
    float L = 0.f;
    #pragma unroll
    for (int s = 0; s < NSPLIT; ++s) {
        ws[s] = __expf(ms[s] - M);
        L += ls[s] * ws[s];
    }
    float invL = 1.f / L;

    for (int e = tid; e < Ee; e += 256) {
        float v = 0.f;
        #pragma unroll
        for (int s = 0; s < NSPLIT; ++s)
            v += ctxp[((size_t)s * Bz + b) * Ee + e] * ws[s];
        cin[(size_t)b * H3 + Hh + e] = v * invL;
    }
    for (int s = tid; s < Ss; s += 256)
        aw_out[b * Ss + s] = __expf(scores[b * Ss + s] - M) * invL;
}

static float* sym(const void* s) {
    void* p = nullptr;
    cudaGetSymbolAddress(&p, s);
    return (float*)p;
}

extern "C" void kernel_launch(void* const* d_in, const int* in_sizes, int n_in,
                              void* d_out, int out_size)
{
    const int*   seq      = (const int*)  d_in[0];
    const float* h0       = (const float*)d_in[1];
    const float* c0       = (const float*)d_in[2];
    const float* enc      = (const float*)d_in[3];
    const float* emb      = (const float*)d_in[4];
    const float* w_ih     = (const float*)d_in[5];
    const float* w_hh     = (const float*)d_in[6];
    const float* b_ih     = (const float*)d_in[7];
    const float* b_hh     = (const float*)d_in[8];
    const float* attn_w   = (const float*)d_in[9];
    const float* concat_w = (const float*)d_in[11];
    const float* concat_b = (const float*)d_in[12];
    const float* out_w    = (const float*)d_in[13];
    const float* out_b    = (const float*)d_in[14];

    float* out    = (float*)d_out;
    float* h_out  = out + (size_t)Bz * Vv;
    float* c_out  = h_out + Bz * Hh;
    float* aw_out = c_out + Bz * Hh;

    float* px     = sym(g_x);
    float* pwt    = sym(g_wt);
    float* ppart  = sym(g_part);
    float* pvpart = sym(g_vpart);
    float* psc    = sym(g_scores);
    float* pcin   = sym(g_cin);
    float* pcc    = sym(g_cc);
    float* pctxp  = sym(g_ctxp);
    float* pml    = sym(g_ml);

    cudaFuncSetAttribute(k_gemm_part<0, 0>, cudaFuncAttributeMaxDynamicSharedMemorySize, G_SMEM_BYTES);
    cudaFuncSetAttribute(k_gemm_part<0, 1>, cudaFuncAttributeMaxDynamicSharedMemorySize, G_SMEM_BYTES);
    cudaFuncSetAttribute(k_gemm_dual,       cudaFuncAttributeMaxDynamicSharedMemorySize, G_SMEM_BYTES);
    cudaFuncSetAttribute(k_vocab64,         cudaFuncAttributeMaxDynamicSharedMemorySize, V_SMEM_BYTES);

    // 1. embedding + attn_w transpose (both independent of everything else)
    gather_k<<<(Bz * Hh) / 256, 256>>>(seq, emb, px);
    transpose_w<<<dim3(Ee / 32, Hh / 32), dim3(32, 8)>>>(attn_w, pwt);

    // 2. LSTM gates: both GEMMs in one launch (z: 0 = w_ih@x, 1 = w_hh@h0)
    k_gemm_dual<<<dim3(H4 / 128, 4, 2), 256, G_SMEM_BYTES>>>(
        w_ih, w_hh, px, h0, ppart, H4, Hh, 8);
    lstm_pw2<<<(Bz * Hh) / 256, 256>>>(ppart, b_ih, b_hh, c0, h_out, c_out, pcin);

    // 3. attention query on transposed weights (fast BLAYOUT0 path),
    //    16 split-K slices x 2 chunks; summed inside att_split
    k_gemm_part<0, 0><<<dim3(Ee / 128, 16), 256, G_SMEM_BYTES>>>(pwt, h_out, ppart, Ee, Hh, 2);

    // 4. single-pass attention, 8 S-splits
    att_split<<<dim3(NSPLIT, Bz), 256>>>(ppart, enc, psc, pctxp, pml);
    att_combine<<<Bz, 256>>>(pctxp, pml, psc, pcin, aw_out);

    // 5. concat GEMM + tanh: fp16 single (feeds only the logits), 6 slices x 16 chunks
    k_gemm_part<0, 1><<<dim3(H3 / 128, 6), 256, G_SMEM_BYTES>>>(concat_w, pcin, ppart, H3, H3, 16);
    reduceN<6><<<(Bz * H3 / 4) / 256, 256>>>(ppart, concat_b, pcc, H3);

    // 6. vocab GEMM: KC=64 fp16 kernel, split-K 3 (750 CTAs), then reduce + bias
    k_vocab64<<<dim3(Vv / 128, 3), 256, V_SMEM_BYTES>>>(out_w, pcc, pvpart, 16);
    reduceV<<<(Bz * Vv / 4) / 256, 256>>>(pvpart, out_b, out);
}